// round 3
// baseline (speedup 1.0000x reference)
#include <cuda_runtime.h>

// Problem constants
#define B_    2
#define SQ_   2048
#define SKV_  2048
#define H_    1024
#define NH_   16
#define HD_   64
#define DQ_   1024
#define MROWS (B_ * SQ_)   // 4096

// Scratch (device globals; no allocation allowed)
__device__ float g_Q[MROWS * H_];      // (B,SQ,H), pre-scaled by 1/sqrt(HD)
__device__ float g_K[B_ * SKV_ * H_];  // (B,SKV,H)
__device__ float g_V[B_ * SKV_ * H_];  // (B,SKV,H)
__device__ float g_O[MROWS * H_];      // (B,SQ,H) attention output
__device__ float g_maskf[B_ * SKV_];   // additive mask: 0 or -1e30
__device__ int   g_mask_is_bytes;      // 1 if mask buffer is byte-packed bools

// ---------------------------------------------------------------------------
// Mask dtype detection + expansion.
// The harness materializes inputs as float32/int32/bf16; jax bool should come
// through as int32 (values 0/1). To be robust we scan the first 1024 int32
// words (4096 bytes — in-bounds under BOTH candidate layouts since the mask
// has 4096 elements): any word not in {0,1} implies byte-packed bools.
// ---------------------------------------------------------------------------
__global__ void mask_detect_kernel(const int* __restrict__ m) {
    __shared__ int bad;
    if (threadIdx.x == 0) bad = 0;
    __syncthreads();
    for (int i = threadIdx.x; i < 1024; i += blockDim.x) {
        unsigned v = (unsigned)m[i];
        if (v > 1u) atomicOr(&bad, 1);
    }
    __syncthreads();
    if (threadIdx.x == 0) g_mask_is_bytes = bad;
}

__global__ void mask_expand_kernel(const void* __restrict__ m) {
    int i = blockIdx.x * blockDim.x + threadIdx.x;
    if (i >= B_ * SKV_) return;
    int v;
    if (g_mask_is_bytes) v = ((const unsigned char*)m)[i];
    else                 v = ((const int*)m)[i];
    g_maskf[i] = v ? -1e30f : 0.0f;
}

// ---------------------------------------------------------------------------
// GEMM: C[M,N] = scale * (A[M,K] @ W[K,N] + bias[N]); row-major everywhere.
// 128x128 block, BK=8, 256 threads, 8x8 microtile (split 4+4 cols/rows for
// conflict-free float4 LDS). Global loads prefetched into registers before
// the barrier so DRAM latency overlaps the previous tile's FMA work.
// ---------------------------------------------------------------------------
__global__ __launch_bounds__(256, 2)
void gemm_bias_kernel(const float* __restrict__ A, const float* __restrict__ W,
                      const float* __restrict__ bias, float* __restrict__ C,
                      int M, int N, int K, float scale) {
    __shared__ float As[8][132];  // [k][row], padded
    __shared__ float Bs[8][128];  // [k][col]

    const int tid = threadIdx.x;
    const int tx = tid & 15;
    const int ty = tid >> 4;
    const int bm = blockIdx.y * 128;
    const int bn = blockIdx.x * 128;

    float acc[8][8];
#pragma unroll
    for (int i = 0; i < 8; i++)
#pragma unroll
        for (int j = 0; j < 8; j++) acc[i][j] = 0.0f;

    const int arow = tid >> 1;          // 0..127
    const int akof = (tid & 1) * 4;     // 0 or 4
    const float* Ag = A + (size_t)(bm + arow) * K + akof;
    const float* Wg = W + (size_t)(tid >> 5) * N + bn + (tid & 31) * 4;

    for (int k0 = 0; k0 < K; k0 += 8) {
        float4 av = *(const float4*)(Ag + k0);
        float4 wv = *(const float4*)(Wg + (size_t)k0 * N);
        __syncthreads();  // previous tile's compute done before overwrite
        As[akof + 0][arow] = av.x;
        As[akof + 1][arow] = av.y;
        As[akof + 2][arow] = av.z;
        As[akof + 3][arow] = av.w;
        *(float4*)&Bs[tid >> 5][(tid & 31) * 4] = wv;
        __syncthreads();
#pragma unroll
        for (int kk = 0; kk < 8; kk++) {
            float a[8], b[8];
            *(float4*)(a)     = *(const float4*)&As[kk][ty * 4];
            *(float4*)(a + 4) = *(const float4*)&As[kk][64 + ty * 4];
            *(float4*)(b)     = *(const float4*)&Bs[kk][tx * 4];
            *(float4*)(b + 4) = *(const float4*)&Bs[kk][64 + tx * 4];
#pragma unroll
            for (int i = 0; i < 8; i++)
#pragma unroll
                for (int j = 0; j < 8; j++)
                    acc[i][j] = fmaf(a[i], b[j], acc[i][j]);
        }
    }

    // Epilogue
    float bsv[8];
#pragma unroll
    for (int j = 0; j < 8; j++) {
        int c = (j < 4) ? (tx * 4 + j) : (64 + tx * 4 + (j - 4));
        bsv[j] = bias[bn + c];
    }
#pragma unroll
    for (int i = 0; i < 8; i++) {
        int r = bm + ((i < 4) ? (ty * 4 + i) : (64 + ty * 4 + (i - 4)));
        float4 o0, o1;
        o0.x = scale * (acc[i][0] + bsv[0]);
        o0.y = scale * (acc[i][1] + bsv[1]);
        o0.z = scale * (acc[i][2] + bsv[2]);
        o0.w = scale * (acc[i][3] + bsv[3]);
        o1.x = scale * (acc[i][4] + bsv[4]);
        o1.y = scale * (acc[i][5] + bsv[5]);
        o1.z = scale * (acc[i][6] + bsv[6]);
        o1.w = scale * (acc[i][7] + bsv[7]);
        *(float4*)(C + (size_t)r * N + bn + tx * 4)      = o0;
        *(float4*)(C + (size_t)r * N + bn + 64 + tx * 4) = o1;
    }
}

// ---------------------------------------------------------------------------
// Flash attention (fp32): one block handles 128 query rows for one (b,h).
// Iterates over KV in 128-row tiles; online softmax; P staged through smem.
// grid = (SQ/128, B*NH), block = 256 threads.
// Q is pre-scaled by 1/sqrt(HD). Masked keys get score -1e30. K/V/mask
// global loads are hoisted into registers before the barrier so DRAM
// latency overlaps the previous tile's PV compute.
// ---------------------------------------------------------------------------
#define ATTN_SMEM_FLOATS (64 * 132 + 64 * 132 + 128 * 68 + 128 * 132 + 128)
#define ATTN_SMEM_BYTES  (ATTN_SMEM_FLOATS * 4)

__global__ __launch_bounds__(256, 1)
void flash_attn_kernel() {
    extern __shared__ float sm[];
    float* Qs = sm;                 // [64][132]  (d-major, transposed)
    float* Ks = Qs + 64 * 132;      // [64][132]  (d-major, transposed)
    float* Vs = Ks + 64 * 132;      // [128][68]  (kv-major)
    float* Ps = Vs + 128 * 68;      // [128][132] (kv-major, transposed P)
    float* Ms = Ps + 128 * 132;     // [128] additive mask (0 or -1e30)

    const int tid = threadIdx.x;
    const int tx = tid & 15;
    const int ty = tid >> 4;
    const int bh = blockIdx.y;
    const int b = bh >> 4;   // / NH_
    const int h = bh & 15;   // % NH_
    const int q0 = blockIdx.x * 128;

    const float* Qg = g_Q + ((size_t)(b * SQ_ + q0)) * H_ + h * HD_;
    const float* Kg = g_K + ((size_t)(b * SKV_)) * H_ + h * HD_;
    const float* Vg = g_V + ((size_t)(b * SKV_)) * H_ + h * HD_;
    const float* mg = g_maskf + b * SKV_;

    // Load Q tile (128 rows x 64 dims), transposed into Qs[d][q]
    for (int idx = tid; idx < 128 * 16; idx += 256) {
        int q = idx >> 4;
        int d4 = (idx & 15) * 4;
        float4 v = *(const float4*)(Qg + (size_t)q * H_ + d4);
        Qs[(d4 + 0) * 132 + q] = v.x;
        Qs[(d4 + 1) * 132 + q] = v.y;
        Qs[(d4 + 2) * 132 + q] = v.z;
        Qs[(d4 + 3) * 132 + q] = v.w;
    }

    float o[8][4];
    float mrun[8], lrun[8];
#pragma unroll
    for (int i = 0; i < 8; i++) {
        mrun[i] = -1e30f;
        lrun[i] = 0.0f;
#pragma unroll
        for (int j = 0; j < 4; j++) o[i][j] = 0.0f;
    }

    for (int kv0 = 0; kv0 < SKV_; kv0 += 128) {
        // ---- Prefetch K/V tile + mask into registers (before the barrier)
        float4 kreg[8], vreg[8];
#pragma unroll
        for (int it = 0; it < 8; it++) {
            int idx = tid + it * 256;
            int kv = idx >> 4;
            int d4 = (idx & 15) * 4;
            kreg[it] = *(const float4*)(Kg + (size_t)(kv0 + kv) * H_ + d4);
            vreg[it] = *(const float4*)(Vg + (size_t)(kv0 + kv) * H_ + d4);
        }
        float mval = 0.0f;
        if (tid < 128) mval = mg[kv0 + tid];

        __syncthreads();  // (A) prev PV done, Qs visible on first iter
#pragma unroll
        for (int it = 0; it < 8; it++) {
            int idx = tid + it * 256;
            int kv = idx >> 4;
            int d4 = (idx & 15) * 4;
            Ks[(d4 + 0) * 132 + kv] = kreg[it].x;
            Ks[(d4 + 1) * 132 + kv] = kreg[it].y;
            Ks[(d4 + 2) * 132 + kv] = kreg[it].z;
            Ks[(d4 + 3) * 132 + kv] = kreg[it].w;
            *(float4*)&Vs[kv * 68 + d4] = vreg[it];
        }
        if (tid < 128) Ms[tid] = mval;
        __syncthreads();  // (B)

        // S = Q K^T (tile 128x128), 8x8 per thread
        float s[8][8];
#pragma unroll
        for (int i = 0; i < 8; i++)
#pragma unroll
            for (int j = 0; j < 8; j++) s[i][j] = 0.0f;

#pragma unroll 4
        for (int d = 0; d < 64; d++) {
            float a[8], kk[8];
            *(float4*)(a)      = *(const float4*)&Qs[d * 132 + ty * 4];
            *(float4*)(a + 4)  = *(const float4*)&Qs[d * 132 + 64 + ty * 4];
            *(float4*)(kk)     = *(const float4*)&Ks[d * 132 + tx * 4];
            *(float4*)(kk + 4) = *(const float4*)&Ks[d * 132 + 64 + tx * 4];
#pragma unroll
            for (int i = 0; i < 8; i++)
#pragma unroll
                for (int j = 0; j < 8; j++)
                    s[i][j] = fmaf(a[i], kk[j], s[i][j]);
        }

        float mc[8];
#pragma unroll
        for (int j = 0; j < 8; j++) {
            int c = (j < 4) ? (tx * 4 + j) : (64 + tx * 4 + (j - 4));
            mc[j] = Ms[c];
        }

        // Online softmax per row (rows owned across the 16 tx lanes)
#pragma unroll
        for (int i = 0; i < 8; i++) {
            float mt = -1e30f;
#pragma unroll
            for (int j = 0; j < 8; j++) {
                s[i][j] += mc[j];
                mt = fmaxf(mt, s[i][j]);
            }
#pragma unroll
            for (int off = 8; off > 0; off >>= 1)
                mt = fmaxf(mt, __shfl_xor_sync(0xffffffffu, mt, off));
            float mn = fmaxf(mrun[i], mt);
            float so = __expf(mrun[i] - mn);
            float sum = 0.0f;
#pragma unroll
            for (int j = 0; j < 8; j++) {
                s[i][j] = __expf(s[i][j] - mn);  // s becomes P
                sum += s[i][j];
            }
#pragma unroll
            for (int off = 8; off > 0; off >>= 1)
                sum += __shfl_xor_sync(0xffffffffu, sum, off);
            lrun[i] = lrun[i] * so + sum;
            mrun[i] = mn;
#pragma unroll
            for (int j = 0; j < 4; j++) o[i][j] *= so;
        }

        // Store P transposed: Ps[kv][q]
#pragma unroll
        for (int j = 0; j < 8; j++) {
            int c = (j < 4) ? (tx * 4 + j) : (64 + tx * 4 + (j - 4));
#pragma unroll
            for (int i = 0; i < 8; i++) {
                int r = (i < 4) ? (ty * 4 + i) : (64 + ty * 4 + (i - 4));
                Ps[c * 132 + r] = s[i][j];
            }
        }
        __syncthreads();  // (C)

        // O += P @ V  (rows 8 x dims 4 per thread)
#pragma unroll 4
        for (int kv = 0; kv < 128; kv++) {
            float pr[8], vv[4];
            *(float4*)(pr)     = *(const float4*)&Ps[kv * 132 + ty * 4];
            *(float4*)(pr + 4) = *(const float4*)&Ps[kv * 132 + 64 + ty * 4];
            *(float4*)(vv)     = *(const float4*)&Vs[kv * 68 + tx * 4];
#pragma unroll
            for (int i = 0; i < 8; i++)
#pragma unroll
                for (int j = 0; j < 4; j++)
                    o[i][j] = fmaf(pr[i], vv[j], o[i][j]);
        }
    }

    // Epilogue: normalize and write (B,SQ,H) layout
    float* Og = g_O + ((size_t)(b * SQ_ + q0)) * H_ + h * HD_;
#pragma unroll
    for (int i = 0; i < 8; i++) {
        int r = (i < 4) ? (ty * 4 + i) : (64 + ty * 4 + (i - 4));
        float inv = 1.0f / lrun[i];
        float4 w = make_float4(o[i][0] * inv, o[i][1] * inv,
                               o[i][2] * inv, o[i][3] * inv);
        *(float4*)(Og + (size_t)r * H_ + tx * 4) = w;
    }
}

// ---------------------------------------------------------------------------
extern "C" void kernel_launch(void* const* d_in, const int* in_sizes, int n_in,
                              void* d_out, int out_size) {
    const float* Xq  = (const float*)d_in[0];
    const float* Xkv = (const float*)d_in[1];
    const void*  mask = d_in[2];
    const float* Wq = (const float*)d_in[3];
    const float* bq = (const float*)d_in[4];
    const float* Wk = (const float*)d_in[5];
    const float* bk = (const float*)d_in[6];
    const float* Wv = (const float*)d_in[7];
    const float* bv = (const float*)d_in[8];
    const float* Wo = (const float*)d_in[9];
    const float* bo = (const float*)d_in[10];
    float* out = (float*)d_out;

    float *Qp, *Kp, *Vp, *Op;
    cudaGetSymbolAddress((void**)&Qp, g_Q);
    cudaGetSymbolAddress((void**)&Kp, g_K);
    cudaGetSymbolAddress((void**)&Vp, g_V);
    cudaGetSymbolAddress((void**)&Op, g_O);

    cudaFuncSetAttribute(flash_attn_kernel,
                         cudaFuncAttributeMaxDynamicSharedMemorySize,
                         ATTN_SMEM_BYTES);

    // Mask prep (dtype-robust)
    mask_detect_kernel<<<1, 256>>>((const int*)mask);
    mask_expand_kernel<<<(B_ * SKV_ + 255) / 256, 256>>>(mask);

    dim3 gblk(256);
    dim3 ggrid(H_ / 128, MROWS / 128);  // (8, 32)

    // Projections (Q pre-scaled by 1/sqrt(HD) = 0.125)
    gemm_bias_kernel<<<ggrid, gblk>>>(Xq,  Wq, bq, Qp, MROWS, H_, DQ_, 0.125f);
    gemm_bias_kernel<<<ggrid, gblk>>>(Xkv, Wk, bk, Kp, MROWS, H_, DQ_, 1.0f);
    gemm_bias_kernel<<<ggrid, gblk>>>(Xkv, Wv, bv, Vp, MROWS, H_, DQ_, 1.0f);

    // Attention
    dim3 agrid(SQ_ / 128, B_ * NH_);  // (16, 32)
    flash_attn_kernel<<<agrid, gblk, ATTN_SMEM_BYTES>>>();

    // Output projection
    gemm_bias_kernel<<<ggrid, gblk>>>(Op, Wo, bo, out, MROWS, DQ_, H_, 1.0f);
}

// round 10
// speedup vs baseline: 2.2097x; 2.2097x over previous
#include <cuda_runtime.h>
#include <cuda_bf16.h>
#include <cstdint>

// Problem constants
#define B_    2
#define SQ_   2048
#define SKV_  2048
#define H_    1024
#define NH_   16
#define HD_   64
#define DQ_   1024
#define MROWS (B_ * SQ_)   // 4096

// ---------------------------------------------------------------------------
// Scratch (device globals; no allocation allowed)
// ---------------------------------------------------------------------------
__device__ float g_Q[MROWS * H_];      // (B,SQ,H), pre-scaled by 1/sqrt(HD)
__device__ float g_K[B_ * SKV_ * H_];  // (B,SKV,H)
__device__ float g_V[B_ * SKV_ * H_];  // (B,SKV,H)
__device__ float g_O[MROWS * H_];      // (B,SQ,H) attention output
__device__ float g_maskf[B_ * SKV_];   // additive mask: 0 or -1e30
__device__ int   g_mask_is_bytes;

// bf16 hi/lo split operands for tensor-core GEMMs
__device__ __nv_bfloat16 g_xq_hi[MROWS * DQ_],  g_xq_lo[MROWS * DQ_];
__device__ __nv_bfloat16 g_xkv_hi[MROWS * DQ_], g_xkv_lo[MROWS * DQ_];
__device__ __nv_bfloat16 g_o_hi[MROWS * H_],    g_o_lo[MROWS * H_];
// weights transposed to [N][K] K-major
__device__ __nv_bfloat16 g_wq_hi[H_ * DQ_], g_wq_lo[H_ * DQ_];
__device__ __nv_bfloat16 g_wk_hi[H_ * DQ_], g_wk_lo[H_ * DQ_];
__device__ __nv_bfloat16 g_wv_hi[H_ * DQ_], g_wv_lo[H_ * DQ_];
__device__ __nv_bfloat16 g_wo_hi[DQ_ * H_], g_wo_lo[DQ_ * H_];

// ---------------------------------------------------------------------------
// PTX helpers (sm_80-era only: valid under generic sm_103 PTX target)
// ---------------------------------------------------------------------------
__device__ __forceinline__ uint32_t smem_u32(const void* p) {
    uint32_t a;
    asm("{ .reg .u64 t; cvta.to.shared.u64 t, %1; cvt.u32.u64 %0, t; }"
        : "=r"(a) : "l"(p));
    return a;
}
__device__ __forceinline__ void cp_async16(uint32_t sdst, const void* gsrc) {
    asm volatile("cp.async.cg.shared.global [%0], [%1], 16;"
                 :: "r"(sdst), "l"(gsrc) : "memory");
}
#define CP_COMMIT() asm volatile("cp.async.commit_group;" ::: "memory")
#define CP_WAIT(n)  asm volatile("cp.async.wait_group %0;" :: "n"(n) : "memory")

__device__ __forceinline__ void ldsm_x4(uint32_t* r, uint32_t addr) {
    asm volatile("ldmatrix.sync.aligned.m8n8.x4.shared.b16 {%0,%1,%2,%3}, [%4];"
                 : "=r"(r[0]), "=r"(r[1]), "=r"(r[2]), "=r"(r[3]) : "r"(addr));
}
__device__ __forceinline__ void mma_bf16(float* c, const uint32_t* a,
                                         const uint32_t* b) {
    asm volatile(
        "mma.sync.aligned.m16n8k16.row.col.f32.bf16.bf16.f32 "
        "{%0,%1,%2,%3}, {%4,%5,%6,%7}, {%8,%9}, {%0,%1,%2,%3};"
        : "+f"(c[0]), "+f"(c[1]), "+f"(c[2]), "+f"(c[3])
        : "r"(a[0]), "r"(a[1]), "r"(a[2]), "r"(a[3]), "r"(b[0]), "r"(b[1]));
}
// pack two fp32 -> bf16x2 (lo = first arg, hi = second; PTX cvt: first src -> hi)
__device__ __forceinline__ uint32_t pack_bf16(float lo, float hi) {
    uint32_t r;
    asm("cvt.rn.bf16x2.f32 %0, %1, %2;" : "=r"(r) : "f"(hi), "f"(lo));
    return r;
}

// ---------------------------------------------------------------------------
// Mask dtype detection + expansion (dtype-robust; verified round 3)
// ---------------------------------------------------------------------------
__global__ void mask_detect_kernel(const int* __restrict__ m) {
    __shared__ int bad;
    if (threadIdx.x == 0) bad = 0;
    __syncthreads();
    for (int i = threadIdx.x; i < 1024; i += blockDim.x) {
        unsigned v = (unsigned)m[i];
        if (v > 1u) atomicOr(&bad, 1);
    }
    __syncthreads();
    if (threadIdx.x == 0) g_mask_is_bytes = bad;
}
__global__ void mask_expand_kernel(const void* __restrict__ m) {
    int i = blockIdx.x * blockDim.x + threadIdx.x;
    if (i >= B_ * SKV_) return;
    int v;
    if (g_mask_is_bytes) v = ((const unsigned char*)m)[i];
    else                 v = ((const int*)m)[i];
    g_maskf[i] = v ? -1e30f : 0.0f;
}

// ---------------------------------------------------------------------------
// fp32 -> bf16 hi/lo split (elementwise, vectorized by 4)
// ---------------------------------------------------------------------------
__global__ void convert_hilo_kernel(const float* __restrict__ in,
                                    __nv_bfloat16* __restrict__ hi,
                                    __nv_bfloat16* __restrict__ lo, int n4) {
    int i = blockIdx.x * blockDim.x + threadIdx.x;
    if (i >= n4) return;
    float4 v = ((const float4*)in)[i];
    __nv_bfloat16 h[4], l[4];
    float f[4] = {v.x, v.y, v.z, v.w};
#pragma unroll
    for (int j = 0; j < 4; j++) {
        h[j] = __float2bfloat16(f[j]);
        l[j] = __float2bfloat16(f[j] - __bfloat162float(h[j]));
    }
    ((uint2*)hi)[i] = *(uint2*)h;
    ((uint2*)lo)[i] = *(uint2*)l;
}

// ---------------------------------------------------------------------------
// W [K x N] fp32 -> Wt [N x K] bf16 hi/lo (transpose through smem)
// ---------------------------------------------------------------------------
__global__ void transpose_convert_kernel(const float* __restrict__ W,
                                         __nv_bfloat16* __restrict__ Thi,
                                         __nv_bfloat16* __restrict__ Tlo,
                                         int Kd, int Nd) {
    __shared__ float tile[32][33];
    int n0 = blockIdx.x * 32, k0 = blockIdx.y * 32;
    int tx = threadIdx.x & 31, ty = threadIdx.x >> 5;
    for (int r = ty; r < 32; r += 8)
        tile[r][tx] = W[(size_t)(k0 + r) * Nd + n0 + tx];
    __syncthreads();
    for (int r = ty; r < 32; r += 8) {
        float v = tile[tx][r];  // = W[k0+tx][n0+r]
        __nv_bfloat16 h = __float2bfloat16(v);
        __nv_bfloat16 l = __float2bfloat16(v - __bfloat162float(h));
        Thi[(size_t)(n0 + r) * Kd + k0 + tx] = h;
        Tlo[(size_t)(n0 + r) * Kd + k0 + tx] = l;
    }
}

// ---------------------------------------------------------------------------
// Split-bf16 tensor-core GEMM via mma.sync (HMMA) — unchanged from R4-R8.
// ---------------------------------------------------------------------------
#define GSTRIDE 80
#define ARR_BYTES (128 * GSTRIDE)
#define STAGE_BYTES (4 * ARR_BYTES)
#define TCG_SMEM (2 * STAGE_BYTES)

__global__ __launch_bounds__(256)
void tc_gemm_kernel(const __nv_bfloat16* __restrict__ Ahi,
                    const __nv_bfloat16* __restrict__ Alo,
                    const __nv_bfloat16* __restrict__ Bhi,
                    const __nv_bfloat16* __restrict__ Blo,
                    const float* __restrict__ bias, float* __restrict__ C,
                    float scale) {
    extern __shared__ char smem[];
    const uint32_t sb = smem_u32(smem);
    const int tid = threadIdx.x;
    const int wid = tid >> 5;
    const int lane = tid & 31;
    const int wm = wid >> 2;
    const int wn = wid & 3;
    const int bm = blockIdx.y * 128;
    const int bn = blockIdx.x * 128;

    const int ld_row = tid >> 2;
    const int ld_seg = tid & 3;

    float acc[4][4][4];
#pragma unroll
    for (int i = 0; i < 4; i++)
#pragma unroll
        for (int j = 0; j < 4; j++)
#pragma unroll
            for (int q = 0; q < 4; q++) acc[i][j][q] = 0.0f;

    auto issue = [&](int ch, int s) {
        const uint32_t so = sb + s * STAGE_BYTES;
        const int kbase = ch * 32;
#pragma unroll
        for (int it = 0; it < 2; it++) {
            int row = ld_row + it * 64;
            uint32_t soff = row * GSTRIDE + ld_seg * 16;
            size_t ga = (size_t)(bm + row) * 1024 + kbase + ld_seg * 8;
            size_t gb = (size_t)(bn + row) * 1024 + kbase + ld_seg * 8;
            cp_async16(so + soff,                 Ahi + ga);
            cp_async16(so + ARR_BYTES + soff,     Alo + ga);
            cp_async16(so + 2 * ARR_BYTES + soff, Bhi + gb);
            cp_async16(so + 3 * ARR_BYTES + soff, Blo + gb);
        }
    };

    issue(0, 0);
    CP_COMMIT();

    const uint32_t a_row = (uint32_t)(wm * 64 + (lane & 15));
    const uint32_t a_kof = (uint32_t)((lane & 16) >> 1);
    const uint32_t b_row = (uint32_t)(wn * 32 + ((lane & 16) >> 1) + (lane & 7));
    const uint32_t b_kof = (uint32_t)(lane & 8);

    for (int ch = 0; ch < 32; ch++) {
        const int s = ch & 1;
        if (ch < 31) { issue(ch + 1, s ^ 1); CP_COMMIT(); CP_WAIT(1); }
        else         { CP_WAIT(0); }
        __syncthreads();

        const uint32_t so = sb + s * STAGE_BYTES;
#pragma unroll
        for (int ks = 0; ks < 32; ks += 16) {
            uint32_t ah[4][4], al[4][4], bh[4][2], bl[4][2];
#pragma unroll
            for (int mt = 0; mt < 4; mt++) {
                uint32_t ao = (a_row + mt * 16) * GSTRIDE + (ks + a_kof) * 2;
                ldsm_x4(ah[mt], so + ao);
                ldsm_x4(al[mt], so + ARR_BYTES + ao);
            }
#pragma unroll
            for (int p = 0; p < 2; p++) {
                uint32_t bo = (b_row + p * 16) * GSTRIDE + (ks + b_kof) * 2;
                uint32_t rh[4], rl[4];
                ldsm_x4(rh, so + 2 * ARR_BYTES + bo);
                ldsm_x4(rl, so + 3 * ARR_BYTES + bo);
                bh[2 * p][0] = rh[0]; bh[2 * p][1] = rh[1];
                bh[2 * p + 1][0] = rh[2]; bh[2 * p + 1][1] = rh[3];
                bl[2 * p][0] = rl[0]; bl[2 * p][1] = rl[1];
                bl[2 * p + 1][0] = rl[2]; bl[2 * p + 1][1] = rl[3];
            }
#pragma unroll
            for (int mt = 0; mt < 4; mt++)
#pragma unroll
                for (int nt = 0; nt < 4; nt++) {
                    mma_bf16(acc[mt][nt], ah[mt], bh[nt]);
                    mma_bf16(acc[mt][nt], ah[mt], bl[nt]);
                    mma_bf16(acc[mt][nt], al[mt], bh[nt]);
                }
        }
        __syncthreads();
    }

    const int gid = lane >> 2;
    const int tig = lane & 3;
#pragma unroll
    for (int mt = 0; mt < 4; mt++) {
        int r0 = bm + wm * 64 + mt * 16 + gid;
#pragma unroll
        for (int nt = 0; nt < 4; nt++) {
            int c0 = bn + wn * 32 + nt * 8 + tig * 2;
            float b0 = __ldg(&bias[c0]), b1 = __ldg(&bias[c0 + 1]);
            float2 v0, v1;
            v0.x = scale * (acc[mt][nt][0] + b0);
            v0.y = scale * (acc[mt][nt][1] + b1);
            v1.x = scale * (acc[mt][nt][2] + b0);
            v1.y = scale * (acc[mt][nt][3] + b1);
            *(float2*)(C + (size_t)r0 * 1024 + c0)       = v0;
            *(float2*)(C + (size_t)(r0 + 8) * 1024 + c0) = v1;
        }
    }
}

// ---------------------------------------------------------------------------
// HMMA flash attention (FA2 layout). 8 warps x 16 q-rows = 128 q per CTA.
// kv tiles of 128. Q/K bf16 hi/lo in smem [row][64] (144B stride);
// V transposed [hd][kv] (272B stride). 3-term split on QK^T and PV.
// Softmax in fp32 registers; P repacked to A-fragments via cvt.bf16x2.
// grid (16, 32), 256 threads, ~109KB smem (1 CTA/SM).
// ---------------------------------------------------------------------------
#define QSTR 144
#define VSTR 272
#define AQH 0
#define AQL (AQH + 128 * QSTR)         // 18432
#define AKH (AQL + 128 * QSTR)         // 36864
#define AKL (AKH + 128 * QSTR)         // 55296
#define AVH (AKL + 128 * QSTR)         // 73728
#define AVL (AVH + 64 * VSTR)          // 91136
#define AMS (AVL + 64 * VSTR)          // 108544
#define ATTN2_SMEM (AMS + 512)         // 109056

__global__ __launch_bounds__(256, 1)
void flash_attn_tc_kernel() {
    extern __shared__ char smem[];
    const uint32_t sb = smem_u32(smem);
    float* Ms = (float*)(smem + AMS);

    const int tid = threadIdx.x;
    const int wid = tid >> 5;
    const int lane = tid & 31;
    const int gid = lane >> 2;     // 0..7
    const int tig = lane & 3;      // 0..3
    const int b = blockIdx.y >> 4;
    const int h = blockIdx.y & 15;
    const int q0 = blockIdx.x * 128;

    const float* Qg = g_Q + ((size_t)(b * SQ_ + q0)) * H_ + h * HD_;
    const float* Kg = g_K + ((size_t)(b * SKV_)) * H_ + h * HD_;
    const float* Vg = g_V + ((size_t)(b * SKV_)) * H_ + h * HD_;
    const float* mg = g_maskf + b * SKV_;

    // ---- Load Q (128x64 fp32), split hi/lo, store to smem [q][d]
    for (int idx = tid; idx < 128 * 16; idx += 256) {
        int q = idx >> 4;
        int d4 = (idx & 15) * 4;
        float4 v = *(const float4*)(Qg + (size_t)q * H_ + d4);
        float f[4] = {v.x, v.y, v.z, v.w};
        __nv_bfloat16 hh[4], ll[4];
#pragma unroll
        for (int j = 0; j < 4; j++) {
            hh[j] = __float2bfloat16(f[j]);
            ll[j] = __float2bfloat16(f[j] - __bfloat162float(hh[j]));
        }
        *(uint2*)(smem + AQH + q * QSTR + d4 * 2) = *(uint2*)hh;
        *(uint2*)(smem + AQL + q * QSTR + d4 * 2) = *(uint2*)ll;
    }
    __syncthreads();

    // ---- Hoist Q fragments (4 k-steps over HD=64)
    const uint32_t a_row = (uint32_t)(wid * 16 + (lane & 15));
    const uint32_t a_kof = (uint32_t)((lane & 16) >> 1);
    const uint32_t b_sel = (uint32_t)(((lane & 16) >> 1) + (lane & 7));
    const uint32_t b_kof = (uint32_t)(lane & 8);
    uint32_t qh[4][4], ql[4][4];
#pragma unroll
    for (int ks = 0; ks < 4; ks++) {
        uint32_t ao = a_row * QSTR + (ks * 16 + a_kof) * 2;
        ldsm_x4(qh[ks], sb + AQH + ao);
        ldsm_x4(ql[ks], sb + AQL + ao);
    }

    // ---- Online softmax state + O accumulator (n-tiles over HD: 8)
    float o[8][4];
#pragma unroll
    for (int nt = 0; nt < 8; nt++)
#pragma unroll
        for (int j = 0; j < 4; j++) o[nt][j] = 0.0f;
    float m0r = -1e30f, m1r = -1e30f, l0r = 0.0f, l1r = 0.0f;

    for (int kv0 = 0; kv0 < SKV_; kv0 += 128) {
        // ---- Prefetch K/V fp32 + mask into registers
        float4 kreg[8], vreg[8];
#pragma unroll
        for (int it = 0; it < 8; it++) {
            int idx = tid + it * 256;
            int kv = idx >> 4;
            int d4 = (idx & 15) * 4;
            kreg[it] = *(const float4*)(Kg + (size_t)(kv0 + kv) * H_ + d4);
            vreg[it] = *(const float4*)(Vg + (size_t)(kv0 + kv) * H_ + d4);
        }
        float mval = 0.0f;
        if (tid < 128) mval = mg[kv0 + tid];

        __syncthreads();  // previous tile fully consumed
        // ---- Convert + store K [kv][d] and V transposed [d][kv]
#pragma unroll
        for (int it = 0; it < 8; it++) {
            int idx = tid + it * 256;
            int kv = idx >> 4;
            int d4 = (idx & 15) * 4;
            float kf[4] = {kreg[it].x, kreg[it].y, kreg[it].z, kreg[it].w};
            __nv_bfloat16 kh[4], kl[4];
#pragma unroll
            for (int j = 0; j < 4; j++) {
                kh[j] = __float2bfloat16(kf[j]);
                kl[j] = __float2bfloat16(kf[j] - __bfloat162float(kh[j]));
            }
            *(uint2*)(smem + AKH + kv * QSTR + d4 * 2) = *(uint2*)kh;
            *(uint2*)(smem + AKL + kv * QSTR + d4 * 2) = *(uint2*)kl;
            float vf[4] = {vreg[it].x, vreg[it].y, vreg[it].z, vreg[it].w};
#pragma unroll
            for (int j = 0; j < 4; j++) {
                __nv_bfloat16 vh = __float2bfloat16(vf[j]);
                __nv_bfloat16 vl = __float2bfloat16(vf[j] - __bfloat162float(vh));
                *(__nv_bfloat16*)(smem + AVH + (d4 + j) * VSTR + kv * 2) = vh;
                *(__nv_bfloat16*)(smem + AVL + (d4 + j) * VSTR + kv * 2) = vl;
            }
        }
        if (tid < 128) Ms[tid] = mval;
        __syncthreads();

        // ---- S = Q K^T : 16 n-tiles (128 kv), 4 k-steps, 3-term split
        float sc[16][4];
#pragma unroll
        for (int nt = 0; nt < 16; nt++)
#pragma unroll
            for (int j = 0; j < 4; j++) sc[nt][j] = 0.0f;
#pragma unroll
        for (int ks = 0; ks < 4; ks++) {
#pragma unroll
            for (int p = 0; p < 8; p++) {
                uint32_t bo = (p * 16 + b_sel) * QSTR + (ks * 16 + b_kof) * 2;
                uint32_t kh4[4], kl4[4];
                ldsm_x4(kh4, sb + AKH + bo);
                ldsm_x4(kl4, sb + AKL + bo);
                uint32_t bh0[2] = {kh4[0], kh4[1]}, bh1[2] = {kh4[2], kh4[3]};
                uint32_t bl0[2] = {kl4[0], kl4[1]}, bl1[2] = {kl4[2], kl4[3]};
                mma_bf16(sc[2 * p],     qh[ks], bh0);
                mma_bf16(sc[2 * p],     qh[ks], bl0);
                mma_bf16(sc[2 * p],     ql[ks], bh0);
                mma_bf16(sc[2 * p + 1], qh[ks], bh1);
                mma_bf16(sc[2 * p + 1], qh[ks], bl1);
                mma_bf16(sc[2 * p + 1], ql[ks], bh1);
            }
        }

        // ---- Mask + online softmax (rows gid and gid+8 per lane)
        float mt0 = -1e30f, mt1 = -1e30f;
#pragma unroll
        for (int nt = 0; nt < 16; nt++) {
            float mk0 = Ms[nt * 8 + tig * 2];
            float mk1 = Ms[nt * 8 + tig * 2 + 1];
            sc[nt][0] += mk0; sc[nt][1] += mk1;
            sc[nt][2] += mk0; sc[nt][3] += mk1;
            mt0 = fmaxf(mt0, fmaxf(sc[nt][0], sc[nt][1]));
            mt1 = fmaxf(mt1, fmaxf(sc[nt][2], sc[nt][3]));
        }
        mt0 = fmaxf(mt0, __shfl_xor_sync(0xffffffffu, mt0, 1));
        mt0 = fmaxf(mt0, __shfl_xor_sync(0xffffffffu, mt0, 2));
        mt1 = fmaxf(mt1, __shfl_xor_sync(0xffffffffu, mt1, 1));
        mt1 = fmaxf(mt1, __shfl_xor_sync(0xffffffffu, mt1, 2));
        float mn0 = fmaxf(m0r, mt0), mn1 = fmaxf(m1r, mt1);
        float so0 = __expf(m0r - mn0), so1 = __expf(m1r - mn1);
        float sum0 = 0.0f, sum1 = 0.0f;
#pragma unroll
        for (int nt = 0; nt < 16; nt++) {
            sc[nt][0] = __expf(sc[nt][0] - mn0);
            sc[nt][1] = __expf(sc[nt][1] - mn0);
            sc[nt][2] = __expf(sc[nt][2] - mn1);
            sc[nt][3] = __expf(sc[nt][3] - mn1);
            sum0 += sc[nt][0] + sc[nt][1];
            sum1 += sc[nt][2] + sc[nt][3];
        }
        sum0 += __shfl_xor_sync(0xffffffffu, sum0, 1);
        sum0 += __shfl_xor_sync(0xffffffffu, sum0, 2);
        sum1 += __shfl_xor_sync(0xffffffffu, sum1, 1);
        sum1 += __shfl_xor_sync(0xffffffffu, sum1, 2);
        l0r = l0r * so0 + sum0;  m0r = mn0;
        l1r = l1r * so1 + sum1;  m1r = mn1;
#pragma unroll
        for (int nt = 0; nt < 8; nt++) {
            o[nt][0] *= so0; o[nt][1] *= so0;
            o[nt][2] *= so1; o[nt][3] *= so1;
        }

        // ---- O += P V : 8 k-steps (kv), 8 n-tiles (hd), 3-term split of P
#pragma unroll
        for (int kt = 0; kt < 8; kt++) {
            // P fragments from score tiles 2kt, 2kt+1 (FA2 register repack)
            uint32_t ph[4], pl[4];
            float c00 = sc[2 * kt][0],     c01 = sc[2 * kt][1];
            float c02 = sc[2 * kt][2],     c03 = sc[2 * kt][3];
            float c10 = sc[2 * kt + 1][0], c11 = sc[2 * kt + 1][1];
            float c12 = sc[2 * kt + 1][2], c13 = sc[2 * kt + 1][3];
            ph[0] = pack_bf16(c00, c01);
            ph[1] = pack_bf16(c02, c03);
            ph[2] = pack_bf16(c10, c11);
            ph[3] = pack_bf16(c12, c13);
            pl[0] = pack_bf16(c00 - __bfloat162float(__float2bfloat16(c00)),
                              c01 - __bfloat162float(__float2bfloat16(c01)));
            pl[1] = pack_bf16(c02 - __bfloat162float(__float2bfloat16(c02)),
                              c03 - __bfloat162float(__float2bfloat16(c03)));
            pl[2] = pack_bf16(c10 - __bfloat162float(__float2bfloat16(c10)),
                              c11 - __bfloat162float(__float2bfloat16(c11)));
            pl[3] = pack_bf16(c12 - __bfloat162float(__float2bfloat16(c12)),
                              c13 - __bfloat162float(__float2bfloat16(c13)));
#pragma unroll
            for (int p = 0; p < 4; p++) {
                uint32_t bo = (p * 16 + b_sel) * VSTR + (kt * 16 + b_kof) * 2;
                uint32_t vh4[4], vl4[4];
                ldsm_x4(vh4, sb + AVH + bo);
                ldsm_x4(vl4, sb + AVL + bo);
                uint32_t bh0[2] = {vh4[0], vh4[1]}, bh1[2] = {vh4[2], vh4[3]};
                uint32_t bl0[2] = {vl4[0], vl4[1]}, bl1[2] = {vl4[2], vl4[3]};
                mma_bf16(o[2 * p],     ph, bh0);
                mma_bf16(o[2 * p],     ph, bl0);
                mma_bf16(o[2 * p],     pl, bh0);
                mma_bf16(o[2 * p + 1], ph, bh1);
                mma_bf16(o[2 * p + 1], ph, bl1);
                mma_bf16(o[2 * p + 1], pl, bh1);
            }
        }
    }

    // ---- Epilogue: normalize, write fp32 (B,SQ,H)
    float inv0 = 1.0f / l0r, inv1 = 1.0f / l1r;
    int r0 = q0 + wid * 16 + gid;
    float* Og = g_O + ((size_t)(b * SQ_ + r0)) * H_ + h * HD_;
#pragma unroll
    for (int nt = 0; nt < 8; nt++) {
        int c = nt * 8 + tig * 2;
        *(float2*)(Og + c) = make_float2(o[nt][0] * inv0, o[nt][1] * inv0);
        *(float2*)(Og + (size_t)8 * H_ + c) =
            make_float2(o[nt][2] * inv1, o[nt][3] * inv1);
    }
}

// ---------------------------------------------------------------------------
extern "C" void kernel_launch(void* const* d_in, const int* in_sizes, int n_in,
                              void* d_out, int out_size) {
    const float* Xq  = (const float*)d_in[0];
    const float* Xkv = (const float*)d_in[1];
    const void*  mask = d_in[2];
    const float* Wq = (const float*)d_in[3];
    const float* bq = (const float*)d_in[4];
    const float* Wk = (const float*)d_in[5];
    const float* bk = (const float*)d_in[6];
    const float* Wv = (const float*)d_in[7];
    const float* bv = (const float*)d_in[8];
    const float* Wo = (const float*)d_in[9];
    const float* bo = (const float*)d_in[10];
    float* out = (float*)d_out;

    float *Qp, *Kp, *Vp, *Op;
    cudaGetSymbolAddress((void**)&Qp, g_Q);
    cudaGetSymbolAddress((void**)&Kp, g_K);
    cudaGetSymbolAddress((void**)&Vp, g_V);
    cudaGetSymbolAddress((void**)&Op, g_O);
    __nv_bfloat16 *xqh, *xql, *xkh, *xkl, *oh, *ol;
    __nv_bfloat16 *wqh, *wql, *wkh, *wkl, *wvh, *wvl, *woh, *wol;
    cudaGetSymbolAddress((void**)&xqh, g_xq_hi);
    cudaGetSymbolAddress((void**)&xql, g_xq_lo);
    cudaGetSymbolAddress((void**)&xkh, g_xkv_hi);
    cudaGetSymbolAddress((void**)&xkl, g_xkv_lo);
    cudaGetSymbolAddress((void**)&oh,  g_o_hi);
    cudaGetSymbolAddress((void**)&ol,  g_o_lo);
    cudaGetSymbolAddress((void**)&wqh, g_wq_hi);
    cudaGetSymbolAddress((void**)&wql, g_wq_lo);
    cudaGetSymbolAddress((void**)&wkh, g_wk_hi);
    cudaGetSymbolAddress((void**)&wkl, g_wk_lo);
    cudaGetSymbolAddress((void**)&wvh, g_wv_hi);
    cudaGetSymbolAddress((void**)&wvl, g_wv_lo);
    cudaGetSymbolAddress((void**)&woh, g_wo_hi);
    cudaGetSymbolAddress((void**)&wol, g_wo_lo);

    cudaFuncSetAttribute(flash_attn_tc_kernel,
                         cudaFuncAttributeMaxDynamicSharedMemorySize,
                         ATTN2_SMEM);
    cudaFuncSetAttribute(tc_gemm_kernel,
                         cudaFuncAttributeMaxDynamicSharedMemorySize,
                         TCG_SMEM);

    // Mask prep
    mask_detect_kernel<<<1, 256>>>((const int*)mask);
    mask_expand_kernel<<<(B_ * SKV_ + 255) / 256, 256>>>(mask);

    // Convert activations (hi/lo split)
    const int n4 = MROWS * DQ_ / 4;
    convert_hilo_kernel<<<(n4 + 255) / 256, 256>>>(Xq, xqh, xql, n4);
    convert_hilo_kernel<<<(n4 + 255) / 256, 256>>>(Xkv, xkh, xkl, n4);

    // Transpose + convert weights to [N][K] bf16 hi/lo
    dim3 tgrid(DQ_ / 32, H_ / 32), tblk(256);
    transpose_convert_kernel<<<tgrid, tblk>>>(Wq, wqh, wql, DQ_, H_);
    transpose_convert_kernel<<<tgrid, tblk>>>(Wk, wkh, wkl, DQ_, H_);
    transpose_convert_kernel<<<tgrid, tblk>>>(Wv, wvh, wvl, DQ_, H_);
    transpose_convert_kernel<<<tgrid, tblk>>>(Wo, woh, wol, H_, DQ_);

    // Projections on tensor cores (Q folds 1/sqrt(HD) = 0.125)
    dim3 ggrid(H_ / 128, MROWS / 128);  // (8, 32)
    tc_gemm_kernel<<<ggrid, 256, TCG_SMEM>>>(xqh, xql, wqh, wql, bq, Qp, 0.125f);
    tc_gemm_kernel<<<ggrid, 256, TCG_SMEM>>>(xkh, xkl, wkh, wkl, bk, Kp, 1.0f);
    tc_gemm_kernel<<<ggrid, 256, TCG_SMEM>>>(xkh, xkl, wvh, wvl, bv, Vp, 1.0f);

    // Attention (HMMA, FA2 layout)
    dim3 agrid(SQ_ / 128, B_ * NH_);  // (16, 32)
    flash_attn_tc_kernel<<<agrid, 256, ATTN2_SMEM>>>();

    // Output projection
    convert_hilo_kernel<<<(n4 + 255) / 256, 256>>>(Op, oh, ol, n4);
    tc_gemm_kernel<<<ggrid, 256, TCG_SMEM>>>(oh, ol, woh, wol, bo, out, 1.0f);
}

// round 12
// speedup vs baseline: 2.6866x; 1.2158x over previous
#include <cuda_runtime.h>
#include <cuda_bf16.h>
#include <cstdint>

// Problem constants
#define B_    2
#define SQ_   2048
#define SKV_  2048
#define H_    1024
#define NH_   16
#define HD_   64
#define DQ_   1024
#define MROWS (B_ * SQ_)   // 4096

// ---------------------------------------------------------------------------
// Scratch (device globals; no allocation allowed)
// ---------------------------------------------------------------------------
__device__ float g_maskf[B_ * SKV_];   // additive mask: 0 or -1e30
__device__ int   g_mask_is_bytes;

// bf16 hi/lo split operands
__device__ __nv_bfloat16 g_xq_hi[MROWS * DQ_],  g_xq_lo[MROWS * DQ_];
__device__ __nv_bfloat16 g_xkv_hi[MROWS * DQ_], g_xkv_lo[MROWS * DQ_];
// projection outputs, bf16 hi/lo (written directly by GEMM epilogue)
__device__ __nv_bfloat16 g_q_hi[MROWS * H_], g_q_lo[MROWS * H_];
__device__ __nv_bfloat16 g_k_hi[MROWS * H_], g_k_lo[MROWS * H_];
__device__ __nv_bfloat16 g_v_hi[MROWS * H_], g_v_lo[MROWS * H_];
// attention output, bf16 hi/lo (written directly by attention epilogue)
__device__ __nv_bfloat16 g_o_hi[MROWS * H_], g_o_lo[MROWS * H_];
// weights transposed to [N][K] K-major
__device__ __nv_bfloat16 g_wq_hi[H_ * DQ_], g_wq_lo[H_ * DQ_];
__device__ __nv_bfloat16 g_wk_hi[H_ * DQ_], g_wk_lo[H_ * DQ_];
__device__ __nv_bfloat16 g_wv_hi[H_ * DQ_], g_wv_lo[H_ * DQ_];
__device__ __nv_bfloat16 g_wo_hi[DQ_ * H_], g_wo_lo[DQ_ * H_];

// ---------------------------------------------------------------------------
// PTX helpers (sm_80-era only: valid under generic sm_103 PTX target)
// ---------------------------------------------------------------------------
__device__ __forceinline__ uint32_t smem_u32(const void* p) {
    uint32_t a;
    asm("{ .reg .u64 t; cvta.to.shared.u64 t, %1; cvt.u32.u64 %0, t; }"
        : "=r"(a) : "l"(p));
    return a;
}
__device__ __forceinline__ void cp_async16(uint32_t sdst, const void* gsrc) {
    asm volatile("cp.async.cg.shared.global [%0], [%1], 16;"
                 :: "r"(sdst), "l"(gsrc) : "memory");
}
#define CP_COMMIT() asm volatile("cp.async.commit_group;" ::: "memory")
#define CP_WAIT(n)  asm volatile("cp.async.wait_group %0;" :: "n"(n) : "memory")

__device__ __forceinline__ void ldsm_x4(uint32_t* r, uint32_t addr) {
    asm volatile("ldmatrix.sync.aligned.m8n8.x4.shared.b16 {%0,%1,%2,%3}, [%4];"
                 : "=r"(r[0]), "=r"(r[1]), "=r"(r[2]), "=r"(r[3]) : "r"(addr));
}
__device__ __forceinline__ void ldsm_x4_trans(uint32_t* r, uint32_t addr) {
    asm volatile("ldmatrix.sync.aligned.m8n8.x4.trans.shared.b16 {%0,%1,%2,%3}, [%4];"
                 : "=r"(r[0]), "=r"(r[1]), "=r"(r[2]), "=r"(r[3]) : "r"(addr));
}
__device__ __forceinline__ void mma_bf16(float* c, const uint32_t* a,
                                         const uint32_t* b) {
    asm volatile(
        "mma.sync.aligned.m16n8k16.row.col.f32.bf16.bf16.f32 "
        "{%0,%1,%2,%3}, {%4,%5,%6,%7}, {%8,%9}, {%0,%1,%2,%3};"
        : "+f"(c[0]), "+f"(c[1]), "+f"(c[2]), "+f"(c[3])
        : "r"(a[0]), "r"(a[1]), "r"(a[2]), "r"(a[3]), "r"(b[0]), "r"(b[1]));
}
// pack two fp32 -> bf16x2 (first arg -> low half)
__device__ __forceinline__ uint32_t pack_bf16(float lo, float hi) {
    uint32_t r;
    asm("cvt.rn.bf16x2.f32 %0, %1, %2;" : "=r"(r) : "f"(hi), "f"(lo));
    return r;
}
__device__ __forceinline__ float bf16_res(float x) {
    return x - __bfloat162float(__float2bfloat16(x));
}

// ---------------------------------------------------------------------------
// Mask dtype detection + expansion (verified round 3)
// ---------------------------------------------------------------------------
__global__ void mask_detect_kernel(const int* __restrict__ m) {
    __shared__ int bad;
    if (threadIdx.x == 0) bad = 0;
    __syncthreads();
    for (int i = threadIdx.x; i < 1024; i += blockDim.x) {
        unsigned v = (unsigned)m[i];
        if (v > 1u) atomicOr(&bad, 1);
    }
    __syncthreads();
    if (threadIdx.x == 0) g_mask_is_bytes = bad;
}
__global__ void mask_expand_kernel(const void* __restrict__ m) {
    int i = blockIdx.x * blockDim.x + threadIdx.x;
    if (i >= B_ * SKV_) return;
    int v;
    if (g_mask_is_bytes) v = ((const unsigned char*)m)[i];
    else                 v = ((const int*)m)[i];
    g_maskf[i] = v ? -1e30f : 0.0f;
}

// ---------------------------------------------------------------------------
// fp32 -> bf16 hi/lo split (elementwise, for kernel inputs)
// ---------------------------------------------------------------------------
__global__ void convert_hilo_kernel(const float* __restrict__ in,
                                    __nv_bfloat16* __restrict__ hi,
                                    __nv_bfloat16* __restrict__ lo, int n4) {
    int i = blockIdx.x * blockDim.x + threadIdx.x;
    if (i >= n4) return;
    float4 v = ((const float4*)in)[i];
    __nv_bfloat16 h[4], l[4];
    float f[4] = {v.x, v.y, v.z, v.w};
#pragma unroll
    for (int j = 0; j < 4; j++) {
        h[j] = __float2bfloat16(f[j]);
        l[j] = __float2bfloat16(f[j] - __bfloat162float(h[j]));
    }
    ((uint2*)hi)[i] = *(uint2*)h;
    ((uint2*)lo)[i] = *(uint2*)l;
}

// ---------------------------------------------------------------------------
// W [K x N] fp32 -> Wt [N x K] bf16 hi/lo (transpose through smem)
// ---------------------------------------------------------------------------
__global__ void transpose_convert_kernel(const float* __restrict__ W,
                                         __nv_bfloat16* __restrict__ Thi,
                                         __nv_bfloat16* __restrict__ Tlo,
                                         int Kd, int Nd) {
    __shared__ float tile[32][33];
    int n0 = blockIdx.x * 32, k0 = blockIdx.y * 32;
    int tx = threadIdx.x & 31, ty = threadIdx.x >> 5;
    for (int r = ty; r < 32; r += 8)
        tile[r][tx] = W[(size_t)(k0 + r) * Nd + n0 + tx];
    __syncthreads();
    for (int r = ty; r < 32; r += 8) {
        float v = tile[tx][r];
        __nv_bfloat16 h = __float2bfloat16(v);
        __nv_bfloat16 l = __float2bfloat16(v - __bfloat162float(h));
        Thi[(size_t)(n0 + r) * Kd + k0 + tx] = h;
        Tlo[(size_t)(n0 + r) * Kd + k0 + tx] = l;
    }
}

// ---------------------------------------------------------------------------
// Split-bf16 tensor-core GEMM (validated R10). Epilogue writes either fp32 C
// or bf16 hi/lo split (Chi/Clo) when split != 0.
// ---------------------------------------------------------------------------
#define GSTRIDE 80
#define ARR_BYTES (128 * GSTRIDE)
#define STAGE_BYTES (4 * ARR_BYTES)
#define TCG_SMEM (2 * STAGE_BYTES)

__global__ __launch_bounds__(256)
void tc_gemm_kernel(const __nv_bfloat16* __restrict__ Ahi,
                    const __nv_bfloat16* __restrict__ Alo,
                    const __nv_bfloat16* __restrict__ Bhi,
                    const __nv_bfloat16* __restrict__ Blo,
                    const float* __restrict__ bias, float* __restrict__ C,
                    __nv_bfloat16* __restrict__ Chi,
                    __nv_bfloat16* __restrict__ Clo,
                    int split, float scale) {
    extern __shared__ char smem[];
    const uint32_t sb = smem_u32(smem);
    const int tid = threadIdx.x;
    const int wid = tid >> 5;
    const int lane = tid & 31;
    const int wm = wid >> 2;
    const int wn = wid & 3;
    const int bm = blockIdx.y * 128;
    const int bn = blockIdx.x * 128;

    const int ld_row = tid >> 2;
    const int ld_seg = tid & 3;

    float acc[4][4][4];
#pragma unroll
    for (int i = 0; i < 4; i++)
#pragma unroll
        for (int j = 0; j < 4; j++)
#pragma unroll
            for (int q = 0; q < 4; q++) acc[i][j][q] = 0.0f;

    auto issue = [&](int ch, int s) {
        const uint32_t so = sb + s * STAGE_BYTES;
        const int kbase = ch * 32;
#pragma unroll
        for (int it = 0; it < 2; it++) {
            int row = ld_row + it * 64;
            uint32_t soff = row * GSTRIDE + ld_seg * 16;
            size_t ga = (size_t)(bm + row) * 1024 + kbase + ld_seg * 8;
            size_t gb = (size_t)(bn + row) * 1024 + kbase + ld_seg * 8;
            cp_async16(so + soff,                 Ahi + ga);
            cp_async16(so + ARR_BYTES + soff,     Alo + ga);
            cp_async16(so + 2 * ARR_BYTES + soff, Bhi + gb);
            cp_async16(so + 3 * ARR_BYTES + soff, Blo + gb);
        }
    };

    issue(0, 0);
    CP_COMMIT();

    const uint32_t a_row = (uint32_t)(wm * 64 + (lane & 15));
    const uint32_t a_kof = (uint32_t)((lane & 16) >> 1);
    const uint32_t b_row = (uint32_t)(wn * 32 + ((lane & 16) >> 1) + (lane & 7));
    const uint32_t b_kof = (uint32_t)(lane & 8);

    for (int ch = 0; ch < 32; ch++) {
        const int s = ch & 1;
        if (ch < 31) { issue(ch + 1, s ^ 1); CP_COMMIT(); CP_WAIT(1); }
        else         { CP_WAIT(0); }
        __syncthreads();

        const uint32_t so = sb + s * STAGE_BYTES;
#pragma unroll
        for (int ks = 0; ks < 32; ks += 16) {
            uint32_t ah[4][4], al[4][4], bh[4][2], bl[4][2];
#pragma unroll
            for (int mt = 0; mt < 4; mt++) {
                uint32_t ao = (a_row + mt * 16) * GSTRIDE + (ks + a_kof) * 2;
                ldsm_x4(ah[mt], so + ao);
                ldsm_x4(al[mt], so + ARR_BYTES + ao);
            }
#pragma unroll
            for (int p = 0; p < 2; p++) {
                uint32_t bo = (b_row + p * 16) * GSTRIDE + (ks + b_kof) * 2;
                uint32_t rh[4], rl[4];
                ldsm_x4(rh, so + 2 * ARR_BYTES + bo);
                ldsm_x4(rl, so + 3 * ARR_BYTES + bo);
                bh[2 * p][0] = rh[0]; bh[2 * p][1] = rh[1];
                bh[2 * p + 1][0] = rh[2]; bh[2 * p + 1][1] = rh[3];
                bl[2 * p][0] = rl[0]; bl[2 * p][1] = rl[1];
                bl[2 * p + 1][0] = rl[2]; bl[2 * p + 1][1] = rl[3];
            }
#pragma unroll
            for (int mt = 0; mt < 4; mt++)
#pragma unroll
                for (int nt = 0; nt < 4; nt++) {
                    mma_bf16(acc[mt][nt], ah[mt], bh[nt]);
                    mma_bf16(acc[mt][nt], ah[mt], bl[nt]);
                    mma_bf16(acc[mt][nt], al[mt], bh[nt]);
                }
        }
        __syncthreads();
    }

    const int gid = lane >> 2;
    const int tig = lane & 3;
#pragma unroll
    for (int mt = 0; mt < 4; mt++) {
        int r0 = bm + wm * 64 + mt * 16 + gid;
#pragma unroll
        for (int nt = 0; nt < 4; nt++) {
            int c0 = bn + wn * 32 + nt * 8 + tig * 2;
            float b0 = __ldg(&bias[c0]), b1 = __ldg(&bias[c0 + 1]);
            float v00 = scale * (acc[mt][nt][0] + b0);
            float v01 = scale * (acc[mt][nt][1] + b1);
            float v10 = scale * (acc[mt][nt][2] + b0);
            float v11 = scale * (acc[mt][nt][3] + b1);
            if (!split) {
                *(float2*)(C + (size_t)r0 * 1024 + c0)       = make_float2(v00, v01);
                *(float2*)(C + (size_t)(r0 + 8) * 1024 + c0) = make_float2(v10, v11);
            } else {
                *(uint32_t*)(Chi + (size_t)r0 * 1024 + c0) = pack_bf16(v00, v01);
                *(uint32_t*)(Clo + (size_t)r0 * 1024 + c0) =
                    pack_bf16(bf16_res(v00), bf16_res(v01));
                *(uint32_t*)(Chi + (size_t)(r0 + 8) * 1024 + c0) = pack_bf16(v10, v11);
                *(uint32_t*)(Clo + (size_t)(r0 + 8) * 1024 + c0) =
                    pack_bf16(bf16_res(v10), bf16_res(v11));
            }
        }
    }
}

// ---------------------------------------------------------------------------
// HMMA flash attention v2: pre-split bf16 Q/K/V in gmem, cp.async loads,
// double-buffered K/V, V via trans-ldmatrix (row-major [kv][d] storage).
// 8 warps x 16 q-rows; kv tiles of 128; 3-term split QK^T and PV.
// smem: Q (2x18432) + 2 KV stages (4x18432 each) + mask = 184832 B, 1 CTA/SM.
// ---------------------------------------------------------------------------
#define RSTR 144
#define AQH2 0
#define AQL2 18432
#define KVST(s) (36864 + (s) * 73728)
#define KVKH 0
#define KVKL 18432
#define KVVH 36864
#define KVVL 55296
#define AMS2 184320
#define ATTN3_SMEM 184832

__global__ __launch_bounds__(256, 1)
void flash_attn_tc_kernel() {
    extern __shared__ char smem[];
    const uint32_t sb = smem_u32(smem);
    float* Ms = (float*)(smem + AMS2);

    const int tid = threadIdx.x;
    const int wid = tid >> 5;
    const int lane = tid & 31;
    const int gid = lane >> 2;
    const int tig = lane & 3;
    const int b = blockIdx.y >> 4;
    const int h = blockIdx.y & 15;
    const int q0 = blockIdx.x * 128;

    const size_t qbase  = ((size_t)(b * SQ_ + q0)) * H_ + h * HD_;
    const size_t kvbase = ((size_t)(b * SKV_)) * H_ + h * HD_;
    const float* mg = g_maskf + b * SKV_;

    // cp.async indexing: idx -> (row, 16B chunk)
    auto issue_kv = [&](int t, int s) {
        const uint32_t base = sb + KVST(s);
        const int kv0 = t * 128;
#pragma unroll
        for (int it = 0; it < 4; it++) {
            int idx = tid + it * 256;       // 0..1023
            int row = idx >> 3, ch = idx & 7;
            uint32_t soff = row * RSTR + ch * 16;
            size_t go = kvbase + (size_t)(kv0 + row) * H_ + ch * 8;
            cp_async16(base + KVKH + soff, g_k_hi + go);
            cp_async16(base + KVKL + soff, g_k_lo + go);
            cp_async16(base + KVVH + soff, g_v_hi + go);
            cp_async16(base + KVVL + soff, g_v_lo + go);
        }
    };

    // Q load (once)
#pragma unroll
    for (int it = 0; it < 4; it++) {
        int idx = tid + it * 256;
        int row = idx >> 3, ch = idx & 7;
        uint32_t soff = row * RSTR + ch * 16;
        size_t go = qbase + (size_t)row * H_ + ch * 8;
        cp_async16(sb + AQH2 + soff, g_q_hi + go);
        cp_async16(sb + AQL2 + soff, g_q_lo + go);
    }
    CP_COMMIT();
    issue_kv(0, 0);
    CP_COMMIT();
    CP_WAIT(0);
    __syncthreads();

    // Hoist Q fragments
    const uint32_t a_row = (uint32_t)(wid * 16 + (lane & 15));
    const uint32_t a_kof = (uint32_t)((lane & 16) >> 1);
    const uint32_t b_sel = (uint32_t)(((lane & 16) >> 1) + (lane & 7));
    const uint32_t b_kof = (uint32_t)(lane & 8);
    const uint32_t v_sel = (uint32_t)(lane & 15);
    const uint32_t v_kof = (uint32_t)((lane >> 4) * 8);
    uint32_t qh[4][4], ql[4][4];
#pragma unroll
    for (int ks = 0; ks < 4; ks++) {
        uint32_t ao = a_row * RSTR + (ks * 16 + a_kof) * 2;
        ldsm_x4(qh[ks], sb + AQH2 + ao);
        ldsm_x4(ql[ks], sb + AQL2 + ao);
    }

    float o[8][4];
#pragma unroll
    for (int nt = 0; nt < 8; nt++)
#pragma unroll
        for (int j = 0; j < 4; j++) o[nt][j] = 0.0f;
    float m0r = -1e30f, m1r = -1e30f, l0r = 0.0f, l1r = 0.0f;

    for (int t = 0; t < 16; t++) {
        const int s = t & 1;
        const uint32_t kvb = sb + KVST(s);

        if (tid < 128) Ms[tid] = mg[t * 128 + tid];
        if (t < 15) { issue_kv(t + 1, s ^ 1); CP_COMMIT(); }
        __syncthreads();  // Ms visible; stage s^1 free of readers

        // ---- S = Q K^T : 16 n-tiles, 4 k-steps, 3-term split
        float sc[16][4];
#pragma unroll
        for (int nt = 0; nt < 16; nt++)
#pragma unroll
            for (int j = 0; j < 4; j++) sc[nt][j] = 0.0f;
#pragma unroll
        for (int ks = 0; ks < 4; ks++) {
#pragma unroll
            for (int p = 0; p < 8; p++) {
                uint32_t bo = (p * 16 + b_sel) * RSTR + (ks * 16 + b_kof) * 2;
                uint32_t kh4[4], kl4[4];
                ldsm_x4(kh4, kvb + KVKH + bo);
                ldsm_x4(kl4, kvb + KVKL + bo);
                uint32_t bh0[2] = {kh4[0], kh4[1]}, bh1[2] = {kh4[2], kh4[3]};
                uint32_t bl0[2] = {kl4[0], kl4[1]}, bl1[2] = {kl4[2], kl4[3]};
                mma_bf16(sc[2 * p],     qh[ks], bh0);
                mma_bf16(sc[2 * p],     qh[ks], bl0);
                mma_bf16(sc[2 * p],     ql[ks], bh0);
                mma_bf16(sc[2 * p + 1], qh[ks], bh1);
                mma_bf16(sc[2 * p + 1], qh[ks], bl1);
                mma_bf16(sc[2 * p + 1], ql[ks], bh1);
            }
        }

        // ---- Mask + online softmax
        float mt0 = -1e30f, mt1 = -1e30f;
#pragma unroll
        for (int nt = 0; nt < 16; nt++) {
            float mk0 = Ms[nt * 8 + tig * 2];
            float mk1 = Ms[nt * 8 + tig * 2 + 1];
            sc[nt][0] += mk0; sc[nt][1] += mk1;
            sc[nt][2] += mk0; sc[nt][3] += mk1;
            mt0 = fmaxf(mt0, fmaxf(sc[nt][0], sc[nt][1]));
            mt1 = fmaxf(mt1, fmaxf(sc[nt][2], sc[nt][3]));
        }
        mt0 = fmaxf(mt0, __shfl_xor_sync(0xffffffffu, mt0, 1));
        mt0 = fmaxf(mt0, __shfl_xor_sync(0xffffffffu, mt0, 2));
        mt1 = fmaxf(mt1, __shfl_xor_sync(0xffffffffu, mt1, 1));
        mt1 = fmaxf(mt1, __shfl_xor_sync(0xffffffffu, mt1, 2));
        float mn0 = fmaxf(m0r, mt0), mn1 = fmaxf(m1r, mt1);
        float so0 = __expf(m0r - mn0), so1 = __expf(m1r - mn1);
        float sum0 = 0.0f, sum1 = 0.0f;
#pragma unroll
        for (int nt = 0; nt < 16; nt++) {
            sc[nt][0] = __expf(sc[nt][0] - mn0);
            sc[nt][1] = __expf(sc[nt][1] - mn0);
            sc[nt][2] = __expf(sc[nt][2] - mn1);
            sc[nt][3] = __expf(sc[nt][3] - mn1);
            sum0 += sc[nt][0] + sc[nt][1];
            sum1 += sc[nt][2] + sc[nt][3];
        }
        sum0 += __shfl_xor_sync(0xffffffffu, sum0, 1);
        sum0 += __shfl_xor_sync(0xffffffffu, sum0, 2);
        sum1 += __shfl_xor_sync(0xffffffffu, sum1, 1);
        sum1 += __shfl_xor_sync(0xffffffffu, sum1, 2);
        l0r = l0r * so0 + sum0;  m0r = mn0;
        l1r = l1r * so1 + sum1;  m1r = mn1;
#pragma unroll
        for (int nt = 0; nt < 8; nt++) {
            o[nt][0] *= so0; o[nt][1] *= so0;
            o[nt][2] *= so1; o[nt][3] *= so1;
        }

        // ---- O += P V (trans-ldmatrix on row-major V)
#pragma unroll
        for (int kt = 0; kt < 8; kt++) {
            uint32_t ph[4], pl[4];
            float c00 = sc[2 * kt][0],     c01 = sc[2 * kt][1];
            float c02 = sc[2 * kt][2],     c03 = sc[2 * kt][3];
            float c10 = sc[2 * kt + 1][0], c11 = sc[2 * kt + 1][1];
            float c12 = sc[2 * kt + 1][2], c13 = sc[2 * kt + 1][3];
            ph[0] = pack_bf16(c00, c01);
            ph[1] = pack_bf16(c02, c03);
            ph[2] = pack_bf16(c10, c11);
            ph[3] = pack_bf16(c12, c13);
            pl[0] = pack_bf16(bf16_res(c00), bf16_res(c01));
            pl[1] = pack_bf16(bf16_res(c02), bf16_res(c03));
            pl[2] = pack_bf16(bf16_res(c10), bf16_res(c11));
            pl[3] = pack_bf16(bf16_res(c12), bf16_res(c13));
#pragma unroll
            for (int p = 0; p < 4; p++) {
                uint32_t bo = (kt * 16 + v_sel) * RSTR + (p * 16 + v_kof) * 2;
                uint32_t vh4[4], vl4[4];
                ldsm_x4_trans(vh4, kvb + KVVH + bo);
                ldsm_x4_trans(vl4, kvb + KVVL + bo);
                uint32_t bh0[2] = {vh4[0], vh4[1]}, bh1[2] = {vh4[2], vh4[3]};
                uint32_t bl0[2] = {vl4[0], vl4[1]}, bl1[2] = {vl4[2], vl4[3]};
                mma_bf16(o[2 * p],     ph, bh0);
                mma_bf16(o[2 * p],     ph, bl0);
                mma_bf16(o[2 * p],     pl, bh0);
                mma_bf16(o[2 * p + 1], ph, bh1);
                mma_bf16(o[2 * p + 1], ph, bl1);
                mma_bf16(o[2 * p + 1], pl, bh1);
            }
        }

        if (t < 15) CP_WAIT(0);  // next tile arrived (per-thread)
        __syncthreads();          // all data visible, compute t done
    }

    // ---- Epilogue: normalize, write bf16 hi/lo
    float inv0 = 1.0f / l0r, inv1 = 1.0f / l1r;
    int r0 = q0 + wid * 16 + gid;
    size_t ob = ((size_t)(b * SQ_ + r0)) * H_ + h * HD_;
#pragma unroll
    for (int nt = 0; nt < 8; nt++) {
        int c = nt * 8 + tig * 2;
        float x0 = o[nt][0] * inv0, x1 = o[nt][1] * inv0;
        float y0 = o[nt][2] * inv1, y1 = o[nt][3] * inv1;
        *(uint32_t*)(g_o_hi + ob + c) = pack_bf16(x0, x1);
        *(uint32_t*)(g_o_lo + ob + c) = pack_bf16(bf16_res(x0), bf16_res(x1));
        *(uint32_t*)(g_o_hi + ob + (size_t)8 * H_ + c) = pack_bf16(y0, y1);
        *(uint32_t*)(g_o_lo + ob + (size_t)8 * H_ + c) =
            pack_bf16(bf16_res(y0), bf16_res(y1));
    }
}

// ---------------------------------------------------------------------------
extern "C" void kernel_launch(void* const* d_in, const int* in_sizes, int n_in,
                              void* d_out, int out_size) {
    const float* Xq  = (const float*)d_in[0];
    const float* Xkv = (const float*)d_in[1];
    const void*  mask = d_in[2];
    const float* Wq = (const float*)d_in[3];
    const float* bq = (const float*)d_in[4];
    const float* Wk = (const float*)d_in[5];
    const float* bk = (const float*)d_in[6];
    const float* Wv = (const float*)d_in[7];
    const float* bv = (const float*)d_in[8];
    const float* Wo = (const float*)d_in[9];
    const float* bo = (const float*)d_in[10];
    float* out = (float*)d_out;

    __nv_bfloat16 *xqh, *xql, *xkh, *xkl;
    __nv_bfloat16 *qhi, *qlo, *khi, *klo, *vhi, *vlo, *ohi, *olo;
    __nv_bfloat16 *wqh, *wql, *wkh, *wkl, *wvh, *wvl, *woh, *wol;
    cudaGetSymbolAddress((void**)&xqh, g_xq_hi);
    cudaGetSymbolAddress((void**)&xql, g_xq_lo);
    cudaGetSymbolAddress((void**)&xkh, g_xkv_hi);
    cudaGetSymbolAddress((void**)&xkl, g_xkv_lo);
    cudaGetSymbolAddress((void**)&qhi, g_q_hi);
    cudaGetSymbolAddress((void**)&qlo, g_q_lo);
    cudaGetSymbolAddress((void**)&khi, g_k_hi);
    cudaGetSymbolAddress((void**)&klo, g_k_lo);
    cudaGetSymbolAddress((void**)&vhi, g_v_hi);
    cudaGetSymbolAddress((void**)&vlo, g_v_lo);
    cudaGetSymbolAddress((void**)&ohi, g_o_hi);
    cudaGetSymbolAddress((void**)&olo, g_o_lo);
    cudaGetSymbolAddress((void**)&wqh, g_wq_hi);
    cudaGetSymbolAddress((void**)&wql, g_wq_lo);
    cudaGetSymbolAddress((void**)&wkh, g_wk_hi);
    cudaGetSymbolAddress((void**)&wkl, g_wk_lo);
    cudaGetSymbolAddress((void**)&wvh, g_wv_hi);
    cudaGetSymbolAddress((void**)&wvl, g_wv_lo);
    cudaGetSymbolAddress((void**)&woh, g_wo_hi);
    cudaGetSymbolAddress((void**)&wol, g_wo_lo);

    cudaFuncSetAttribute(flash_attn_tc_kernel,
                         cudaFuncAttributeMaxDynamicSharedMemorySize,
                         ATTN3_SMEM);
    cudaFuncSetAttribute(tc_gemm_kernel,
                         cudaFuncAttributeMaxDynamicSharedMemorySize,
                         TCG_SMEM);

    // Mask prep
    mask_detect_kernel<<<1, 256>>>((const int*)mask);
    mask_expand_kernel<<<(B_ * SKV_ + 255) / 256, 256>>>(mask);

    // Convert input activations (hi/lo split)
    const int n4 = MROWS * DQ_ / 4;
    convert_hilo_kernel<<<(n4 + 255) / 256, 256>>>(Xq, xqh, xql, n4);
    convert_hilo_kernel<<<(n4 + 255) / 256, 256>>>(Xkv, xkh, xkl, n4);

    // Transpose + convert weights to [N][K] bf16 hi/lo
    dim3 tgrid(DQ_ / 32, H_ / 32), tblk(256);
    transpose_convert_kernel<<<tgrid, tblk>>>(Wq, wqh, wql, DQ_, H_);
    transpose_convert_kernel<<<tgrid, tblk>>>(Wk, wkh, wkl, DQ_, H_);
    transpose_convert_kernel<<<tgrid, tblk>>>(Wv, wvh, wvl, DQ_, H_);
    transpose_convert_kernel<<<tgrid, tblk>>>(Wo, woh, wol, H_, DQ_);

    // Projections: split bf16 outputs (Q folds 1/sqrt(HD) = 0.125)
    dim3 ggrid(H_ / 128, MROWS / 128);  // (8, 32)
    tc_gemm_kernel<<<ggrid, 256, TCG_SMEM>>>(xqh, xql, wqh, wql, bq,
                                             nullptr, qhi, qlo, 1, 0.125f);
    tc_gemm_kernel<<<ggrid, 256, TCG_SMEM>>>(xkh, xkl, wkh, wkl, bk,
                                             nullptr, khi, klo, 1, 1.0f);
    tc_gemm_kernel<<<ggrid, 256, TCG_SMEM>>>(xkh, xkl, wvh, wvl, bv,
                                             nullptr, vhi, vlo, 1, 1.0f);

    // Attention (HMMA, pre-split operands, double-buffered cp.async)
    dim3 agrid(SQ_ / 128, B_ * NH_);  // (16, 32)
    flash_attn_tc_kernel<<<agrid, 256, ATTN3_SMEM>>>();

    // Output projection (fp32 out)
    tc_gemm_kernel<<<ggrid, 256, TCG_SMEM>>>(ohi, olo, woh, wol, bo,
                                             out, nullptr, nullptr, 0, 1.0f);
}

// round 14
// speedup vs baseline: 3.0794x; 1.1462x over previous
#include <cuda_runtime.h>
#include <cuda_bf16.h>
#include <cuda_fp16.h>
#include <cstdint>

// Problem constants
#define B_    2
#define SQ_   2048
#define SKV_  2048
#define H_    1024
#define NH_   16
#define HD_   64
#define DQ_   1024
#define MROWS (B_ * SQ_)   // 4096

// ---------------------------------------------------------------------------
// Scratch (device globals; no allocation allowed)
// ---------------------------------------------------------------------------
__device__ float g_maskf[B_ * SKV_];   // additive mask: 0 or -1e30
__device__ int   g_mask_is_bytes;

// bf16 hi/lo split operands
__device__ __nv_bfloat16 g_xq_hi[MROWS * DQ_],  g_xq_lo[MROWS * DQ_];
__device__ __nv_bfloat16 g_xkv_hi[MROWS * DQ_], g_xkv_lo[MROWS * DQ_];
// projection outputs: Q/K split bf16; V plain fp16 (PV runs fp16 single-term)
__device__ __nv_bfloat16 g_q_hi[MROWS * H_], g_q_lo[MROWS * H_];
__device__ __nv_bfloat16 g_k_hi[MROWS * H_], g_k_lo[MROWS * H_];
__device__ __half        g_v_f16[MROWS * H_];
// attention output, bf16 hi/lo
__device__ __nv_bfloat16 g_o_hi[MROWS * H_], g_o_lo[MROWS * H_];
// weights transposed to [N][K] K-major
__device__ __nv_bfloat16 g_wq_hi[H_ * DQ_], g_wq_lo[H_ * DQ_];
__device__ __nv_bfloat16 g_wk_hi[H_ * DQ_], g_wk_lo[H_ * DQ_];
__device__ __nv_bfloat16 g_wv_hi[H_ * DQ_], g_wv_lo[H_ * DQ_];
__device__ __nv_bfloat16 g_wo_hi[DQ_ * H_], g_wo_lo[DQ_ * H_];

// ---------------------------------------------------------------------------
// PTX helpers (sm_80-era only: valid under generic sm_103 PTX target)
// ---------------------------------------------------------------------------
__device__ __forceinline__ uint32_t smem_u32(const void* p) {
    uint32_t a;
    asm("{ .reg .u64 t; cvta.to.shared.u64 t, %1; cvt.u32.u64 %0, t; }"
        : "=r"(a) : "l"(p));
    return a;
}
__device__ __forceinline__ void cp_async16(uint32_t sdst, const void* gsrc) {
    asm volatile("cp.async.cg.shared.global [%0], [%1], 16;"
                 :: "r"(sdst), "l"(gsrc) : "memory");
}
#define CP_COMMIT() asm volatile("cp.async.commit_group;" ::: "memory")
#define CP_WAIT(n)  asm volatile("cp.async.wait_group %0;" :: "n"(n) : "memory")

__device__ __forceinline__ void ldsm_x4(uint32_t* r, uint32_t addr) {
    asm volatile("ldmatrix.sync.aligned.m8n8.x4.shared.b16 {%0,%1,%2,%3}, [%4];"
                 : "=r"(r[0]), "=r"(r[1]), "=r"(r[2]), "=r"(r[3]) : "r"(addr));
}
__device__ __forceinline__ void ldsm_x4_trans(uint32_t* r, uint32_t addr) {
    asm volatile("ldmatrix.sync.aligned.m8n8.x4.trans.shared.b16 {%0,%1,%2,%3}, [%4];"
                 : "=r"(r[0]), "=r"(r[1]), "=r"(r[2]), "=r"(r[3]) : "r"(addr));
}
__device__ __forceinline__ void mma_bf16(float* c, const uint32_t* a,
                                         const uint32_t* b) {
    asm volatile(
        "mma.sync.aligned.m16n8k16.row.col.f32.bf16.bf16.f32 "
        "{%0,%1,%2,%3}, {%4,%5,%6,%7}, {%8,%9}, {%0,%1,%2,%3};"
        : "+f"(c[0]), "+f"(c[1]), "+f"(c[2]), "+f"(c[3])
        : "r"(a[0]), "r"(a[1]), "r"(a[2]), "r"(a[3]), "r"(b[0]), "r"(b[1]));
}
__device__ __forceinline__ void mma_f16(float* c, const uint32_t* a,
                                        const uint32_t* b) {
    asm volatile(
        "mma.sync.aligned.m16n8k16.row.col.f32.f16.f16.f32 "
        "{%0,%1,%2,%3}, {%4,%5,%6,%7}, {%8,%9}, {%0,%1,%2,%3};"
        : "+f"(c[0]), "+f"(c[1]), "+f"(c[2]), "+f"(c[3])
        : "r"(a[0]), "r"(a[1]), "r"(a[2]), "r"(a[3]), "r"(b[0]), "r"(b[1]));
}
// pack two fp32 -> bf16x2 (first arg -> low half)
__device__ __forceinline__ uint32_t pack_bf16(float lo, float hi) {
    uint32_t r;
    asm("cvt.rn.bf16x2.f32 %0, %1, %2;" : "=r"(r) : "f"(hi), "f"(lo));
    return r;
}
// pack two fp32 -> f16x2 (first arg -> low half)
__device__ __forceinline__ uint32_t pack_f16(float lo, float hi) {
    __half2 h2 = __floats2half2_rn(lo, hi);
    return *(uint32_t*)&h2;
}
__device__ __forceinline__ float bf16_res(float x) {
    return x - __bfloat162float(__float2bfloat16(x));
}

// ---------------------------------------------------------------------------
// Mask dtype detection + expansion (verified round 3)
// ---------------------------------------------------------------------------
__global__ void mask_detect_kernel(const int* __restrict__ m) {
    __shared__ int bad;
    if (threadIdx.x == 0) bad = 0;
    __syncthreads();
    for (int i = threadIdx.x; i < 1024; i += blockDim.x) {
        unsigned v = (unsigned)m[i];
        if (v > 1u) atomicOr(&bad, 1);
    }
    __syncthreads();
    if (threadIdx.x == 0) g_mask_is_bytes = bad;
}
__global__ void mask_expand_kernel(const void* __restrict__ m) {
    int i = blockIdx.x * blockDim.x + threadIdx.x;
    if (i >= B_ * SKV_) return;
    int v;
    if (g_mask_is_bytes) v = ((const unsigned char*)m)[i];
    else                 v = ((const int*)m)[i];
    g_maskf[i] = v ? -1e30f : 0.0f;
}

// ---------------------------------------------------------------------------
// fp32 -> bf16 hi/lo split (elementwise, for kernel inputs)
// ---------------------------------------------------------------------------
__global__ void convert_hilo_kernel(const float* __restrict__ in,
                                    __nv_bfloat16* __restrict__ hi,
                                    __nv_bfloat16* __restrict__ lo, int n4) {
    int i = blockIdx.x * blockDim.x + threadIdx.x;
    if (i >= n4) return;
    float4 v = ((const float4*)in)[i];
    __nv_bfloat16 h[4], l[4];
    float f[4] = {v.x, v.y, v.z, v.w};
#pragma unroll
    for (int j = 0; j < 4; j++) {
        h[j] = __float2bfloat16(f[j]);
        l[j] = __float2bfloat16(f[j] - __bfloat162float(h[j]));
    }
    ((uint2*)hi)[i] = *(uint2*)h;
    ((uint2*)lo)[i] = *(uint2*)l;
}

// ---------------------------------------------------------------------------
// W [K x N] fp32 -> Wt [N x K] bf16 hi/lo (transpose through smem)
// ---------------------------------------------------------------------------
__global__ void transpose_convert_kernel(const float* __restrict__ W,
                                         __nv_bfloat16* __restrict__ Thi,
                                         __nv_bfloat16* __restrict__ Tlo,
                                         int Kd, int Nd) {
    __shared__ float tile[32][33];
    int n0 = blockIdx.x * 32, k0 = blockIdx.y * 32;
    int tx = threadIdx.x & 31, ty = threadIdx.x >> 5;
    for (int r = ty; r < 32; r += 8)
        tile[r][tx] = W[(size_t)(k0 + r) * Nd + n0 + tx];
    __syncthreads();
    for (int r = ty; r < 32; r += 8) {
        float v = tile[tx][r];
        __nv_bfloat16 h = __float2bfloat16(v);
        __nv_bfloat16 l = __float2bfloat16(v - __bfloat162float(h));
        Thi[(size_t)(n0 + r) * Kd + k0 + tx] = h;
        Tlo[(size_t)(n0 + r) * Kd + k0 + tx] = l;
    }
}

// ---------------------------------------------------------------------------
// Split-bf16 tensor-core GEMM (validated R10/R12).
// Epilogue mode: 0 = fp32 C, 1 = bf16 hi/lo split (Chi/Clo), 2 = fp16 (Cf16).
// ---------------------------------------------------------------------------
#define GSTRIDE 80
#define ARR_BYTES (128 * GSTRIDE)
#define STAGE_BYTES (4 * ARR_BYTES)
#define TCG_SMEM (2 * STAGE_BYTES)

__global__ __launch_bounds__(256)
void tc_gemm_kernel(const __nv_bfloat16* __restrict__ Ahi,
                    const __nv_bfloat16* __restrict__ Alo,
                    const __nv_bfloat16* __restrict__ Bhi,
                    const __nv_bfloat16* __restrict__ Blo,
                    const float* __restrict__ bias, float* __restrict__ C,
                    __nv_bfloat16* __restrict__ Chi,
                    __nv_bfloat16* __restrict__ Clo,
                    __half* __restrict__ Cf16,
                    int mode, float scale) {
    extern __shared__ char smem[];
    const uint32_t sb = smem_u32(smem);
    const int tid = threadIdx.x;
    const int wid = tid >> 5;
    const int lane = tid & 31;
    const int wm = wid >> 2;
    const int wn = wid & 3;
    const int bm = blockIdx.y * 128;
    const int bn = blockIdx.x * 128;

    const int ld_row = tid >> 2;
    const int ld_seg = tid & 3;

    float acc[4][4][4];
#pragma unroll
    for (int i = 0; i < 4; i++)
#pragma unroll
        for (int j = 0; j < 4; j++)
#pragma unroll
            for (int q = 0; q < 4; q++) acc[i][j][q] = 0.0f;

    auto issue = [&](int ch, int s) {
        const uint32_t so = sb + s * STAGE_BYTES;
        const int kbase = ch * 32;
#pragma unroll
        for (int it = 0; it < 2; it++) {
            int row = ld_row + it * 64;
            uint32_t soff = row * GSTRIDE + ld_seg * 16;
            size_t ga = (size_t)(bm + row) * 1024 + kbase + ld_seg * 8;
            size_t gb = (size_t)(bn + row) * 1024 + kbase + ld_seg * 8;
            cp_async16(so + soff,                 Ahi + ga);
            cp_async16(so + ARR_BYTES + soff,     Alo + ga);
            cp_async16(so + 2 * ARR_BYTES + soff, Bhi + gb);
            cp_async16(so + 3 * ARR_BYTES + soff, Blo + gb);
        }
    };

    issue(0, 0);
    CP_COMMIT();

    const uint32_t a_row = (uint32_t)(wm * 64 + (lane & 15));
    const uint32_t a_kof = (uint32_t)((lane & 16) >> 1);
    const uint32_t b_row = (uint32_t)(wn * 32 + ((lane & 16) >> 1) + (lane & 7));
    const uint32_t b_kof = (uint32_t)(lane & 8);

    for (int ch = 0; ch < 32; ch++) {
        const int s = ch & 1;
        if (ch < 31) { issue(ch + 1, s ^ 1); CP_COMMIT(); CP_WAIT(1); }
        else         { CP_WAIT(0); }
        __syncthreads();

        const uint32_t so = sb + s * STAGE_BYTES;
#pragma unroll
        for (int ks = 0; ks < 32; ks += 16) {
            uint32_t ah[4][4], al[4][4], bh[4][2], bl[4][2];
#pragma unroll
            for (int mt = 0; mt < 4; mt++) {
                uint32_t ao = (a_row + mt * 16) * GSTRIDE + (ks + a_kof) * 2;
                ldsm_x4(ah[mt], so + ao);
                ldsm_x4(al[mt], so + ARR_BYTES + ao);
            }
#pragma unroll
            for (int p = 0; p < 2; p++) {
                uint32_t bo = (b_row + p * 16) * GSTRIDE + (ks + b_kof) * 2;
                uint32_t rh[4], rl[4];
                ldsm_x4(rh, so + 2 * ARR_BYTES + bo);
                ldsm_x4(rl, so + 3 * ARR_BYTES + bo);
                bh[2 * p][0] = rh[0]; bh[2 * p][1] = rh[1];
                bh[2 * p + 1][0] = rh[2]; bh[2 * p + 1][1] = rh[3];
                bl[2 * p][0] = rl[0]; bl[2 * p][1] = rl[1];
                bl[2 * p + 1][0] = rl[2]; bl[2 * p + 1][1] = rl[3];
            }
#pragma unroll
            for (int mt = 0; mt < 4; mt++)
#pragma unroll
                for (int nt = 0; nt < 4; nt++) {
                    mma_bf16(acc[mt][nt], ah[mt], bh[nt]);
                    mma_bf16(acc[mt][nt], ah[mt], bl[nt]);
                    mma_bf16(acc[mt][nt], al[mt], bh[nt]);
                }
        }
        __syncthreads();
    }

    const int gid = lane >> 2;
    const int tig = lane & 3;
#pragma unroll
    for (int mt = 0; mt < 4; mt++) {
        int r0 = bm + wm * 64 + mt * 16 + gid;
#pragma unroll
        for (int nt = 0; nt < 4; nt++) {
            int c0 = bn + wn * 32 + nt * 8 + tig * 2;
            float b0 = __ldg(&bias[c0]), b1 = __ldg(&bias[c0 + 1]);
            float v00 = scale * (acc[mt][nt][0] + b0);
            float v01 = scale * (acc[mt][nt][1] + b1);
            float v10 = scale * (acc[mt][nt][2] + b0);
            float v11 = scale * (acc[mt][nt][3] + b1);
            if (mode == 0) {
                *(float2*)(C + (size_t)r0 * 1024 + c0)       = make_float2(v00, v01);
                *(float2*)(C + (size_t)(r0 + 8) * 1024 + c0) = make_float2(v10, v11);
            } else if (mode == 1) {
                *(uint32_t*)(Chi + (size_t)r0 * 1024 + c0) = pack_bf16(v00, v01);
                *(uint32_t*)(Clo + (size_t)r0 * 1024 + c0) =
                    pack_bf16(bf16_res(v00), bf16_res(v01));
                *(uint32_t*)(Chi + (size_t)(r0 + 8) * 1024 + c0) = pack_bf16(v10, v11);
                *(uint32_t*)(Clo + (size_t)(r0 + 8) * 1024 + c0) =
                    pack_bf16(bf16_res(v10), bf16_res(v11));
            } else {
                *(uint32_t*)(Cf16 + (size_t)r0 * 1024 + c0)       = pack_f16(v00, v01);
                *(uint32_t*)(Cf16 + (size_t)(r0 + 8) * 1024 + c0) = pack_f16(v10, v11);
            }
        }
    }
}

// ---------------------------------------------------------------------------
// HMMA flash attention v3: QK^T split-bf16 (3-term), PV fp16 single-term.
// Pre-split bf16 Q/K + fp16 V in gmem, cp.async double-buffered K/V,
// V via trans-ldmatrix. smem: Q 36864 + 2 stages x (Khi+Klo+Vf16 = 55296)
// + mask 512 = 147968 B, 1 CTA/SM.
// ---------------------------------------------------------------------------
#define RSTR 144
#define AQH2 0
#define AQL2 18432
#define KVST(s) (36864 + (s) * 55296)
#define KVKH 0
#define KVKL 18432
#define KVVF 36864
#define AMS2 147456
#define ATTN4_SMEM 147968

__global__ __launch_bounds__(256, 1)
void flash_attn_tc_kernel() {
    extern __shared__ char smem[];
    const uint32_t sb = smem_u32(smem);
    float* Ms = (float*)(smem + AMS2);

    const int tid = threadIdx.x;
    const int wid = tid >> 5;
    const int lane = tid & 31;
    const int gid = lane >> 2;
    const int tig = lane & 3;
    const int b = blockIdx.y >> 4;
    const int h = blockIdx.y & 15;
    const int q0 = blockIdx.x * 128;

    const size_t qbase  = ((size_t)(b * SQ_ + q0)) * H_ + h * HD_;
    const size_t kvbase = ((size_t)(b * SKV_)) * H_ + h * HD_;
    const float* mg = g_maskf + b * SKV_;

    auto issue_kv = [&](int t, int s) {
        const uint32_t base = sb + KVST(s);
        const int kv0 = t * 128;
#pragma unroll
        for (int it = 0; it < 4; it++) {
            int idx = tid + it * 256;       // 0..1023
            int row = idx >> 3, ch = idx & 7;
            uint32_t soff = row * RSTR + ch * 16;
            size_t go = kvbase + (size_t)(kv0 + row) * H_ + ch * 8;
            cp_async16(base + KVKH + soff, g_k_hi + go);
            cp_async16(base + KVKL + soff, g_k_lo + go);
            cp_async16(base + KVVF + soff, g_v_f16 + go);
        }
    };

    // Q load (once)
#pragma unroll
    for (int it = 0; it < 4; it++) {
        int idx = tid + it * 256;
        int row = idx >> 3, ch = idx & 7;
        uint32_t soff = row * RSTR + ch * 16;
        size_t go = qbase + (size_t)row * H_ + ch * 8;
        cp_async16(sb + AQH2 + soff, g_q_hi + go);
        cp_async16(sb + AQL2 + soff, g_q_lo + go);
    }
    CP_COMMIT();
    issue_kv(0, 0);
    CP_COMMIT();
    CP_WAIT(0);
    __syncthreads();

    // Hoist Q fragments
    const uint32_t a_row = (uint32_t)(wid * 16 + (lane & 15));
    const uint32_t a_kof = (uint32_t)((lane & 16) >> 1);
    const uint32_t b_sel = (uint32_t)(((lane & 16) >> 1) + (lane & 7));
    const uint32_t b_kof = (uint32_t)(lane & 8);
    const uint32_t v_sel = (uint32_t)(lane & 15);
    const uint32_t v_kof = (uint32_t)((lane >> 4) * 8);
    uint32_t qh[4][4], ql[4][4];
#pragma unroll
    for (int ks = 0; ks < 4; ks++) {
        uint32_t ao = a_row * RSTR + (ks * 16 + a_kof) * 2;
        ldsm_x4(qh[ks], sb + AQH2 + ao);
        ldsm_x4(ql[ks], sb + AQL2 + ao);
    }

    float o[8][4];
#pragma unroll
    for (int nt = 0; nt < 8; nt++)
#pragma unroll
        for (int j = 0; j < 4; j++) o[nt][j] = 0.0f;
    float m0r = -1e30f, m1r = -1e30f, l0r = 0.0f, l1r = 0.0f;

    for (int t = 0; t < 16; t++) {
        const int s = t & 1;
        const uint32_t kvb = sb + KVST(s);

        if (tid < 128) Ms[tid] = mg[t * 128 + tid];
        if (t < 15) { issue_kv(t + 1, s ^ 1); CP_COMMIT(); }
        __syncthreads();  // Ms visible; stage s^1 free of readers

        // ---- S = Q K^T : 16 n-tiles, 4 k-steps, 3-term split
        float sc[16][4];
#pragma unroll
        for (int nt = 0; nt < 16; nt++)
#pragma unroll
            for (int j = 0; j < 4; j++) sc[nt][j] = 0.0f;
#pragma unroll
        for (int ks = 0; ks < 4; ks++) {
#pragma unroll
            for (int p = 0; p < 8; p++) {
                uint32_t bo = (p * 16 + b_sel) * RSTR + (ks * 16 + b_kof) * 2;
                uint32_t kh4[4], kl4[4];
                ldsm_x4(kh4, kvb + KVKH + bo);
                ldsm_x4(kl4, kvb + KVKL + bo);
                uint32_t bh0[2] = {kh4[0], kh4[1]}, bh1[2] = {kh4[2], kh4[3]};
                uint32_t bl0[2] = {kl4[0], kl4[1]}, bl1[2] = {kl4[2], kl4[3]};
                mma_bf16(sc[2 * p],     qh[ks], bh0);
                mma_bf16(sc[2 * p],     qh[ks], bl0);
                mma_bf16(sc[2 * p],     ql[ks], bh0);
                mma_bf16(sc[2 * p + 1], qh[ks], bh1);
                mma_bf16(sc[2 * p + 1], qh[ks], bl1);
                mma_bf16(sc[2 * p + 1], ql[ks], bh1);
            }
        }

        // ---- Mask + online softmax
        float mt0 = -1e30f, mt1 = -1e30f;
#pragma unroll
        for (int nt = 0; nt < 16; nt++) {
            float mk0 = Ms[nt * 8 + tig * 2];
            float mk1 = Ms[nt * 8 + tig * 2 + 1];
            sc[nt][0] += mk0; sc[nt][1] += mk1;
            sc[nt][2] += mk0; sc[nt][3] += mk1;
            mt0 = fmaxf(mt0, fmaxf(sc[nt][0], sc[nt][1]));
            mt1 = fmaxf(mt1, fmaxf(sc[nt][2], sc[nt][3]));
        }
        mt0 = fmaxf(mt0, __shfl_xor_sync(0xffffffffu, mt0, 1));
        mt0 = fmaxf(mt0, __shfl_xor_sync(0xffffffffu, mt0, 2));
        mt1 = fmaxf(mt1, __shfl_xor_sync(0xffffffffu, mt1, 1));
        mt1 = fmaxf(mt1, __shfl_xor_sync(0xffffffffu, mt1, 2));
        float mn0 = fmaxf(m0r, mt0), mn1 = fmaxf(m1r, mt1);
        float so0 = __expf(m0r - mn0), so1 = __expf(m1r - mn1);
        float sum0 = 0.0f, sum1 = 0.0f;
#pragma unroll
        for (int nt = 0; nt < 16; nt++) {
            sc[nt][0] = __expf(sc[nt][0] - mn0);
            sc[nt][1] = __expf(sc[nt][1] - mn0);
            sc[nt][2] = __expf(sc[nt][2] - mn1);
            sc[nt][3] = __expf(sc[nt][3] - mn1);
            sum0 += sc[nt][0] + sc[nt][1];
            sum1 += sc[nt][2] + sc[nt][3];
        }
        sum0 += __shfl_xor_sync(0xffffffffu, sum0, 1);
        sum0 += __shfl_xor_sync(0xffffffffu, sum0, 2);
        sum1 += __shfl_xor_sync(0xffffffffu, sum1, 1);
        sum1 += __shfl_xor_sync(0xffffffffu, sum1, 2);
        l0r = l0r * so0 + sum0;  m0r = mn0;
        l1r = l1r * so1 + sum1;  m1r = mn1;
#pragma unroll
        for (int nt = 0; nt < 8; nt++) {
            o[nt][0] *= so0; o[nt][1] *= so0;
            o[nt][2] *= so1; o[nt][3] *= so1;
        }

        // ---- O += P V : fp16 P, fp16 V, single term
#pragma unroll
        for (int kt = 0; kt < 8; kt++) {
            uint32_t ph[4];
            ph[0] = pack_f16(sc[2 * kt][0],     sc[2 * kt][1]);
            ph[1] = pack_f16(sc[2 * kt][2],     sc[2 * kt][3]);
            ph[2] = pack_f16(sc[2 * kt + 1][0], sc[2 * kt + 1][1]);
            ph[3] = pack_f16(sc[2 * kt + 1][2], sc[2 * kt + 1][3]);
#pragma unroll
            for (int p = 0; p < 4; p++) {
                uint32_t bo = (kt * 16 + v_sel) * RSTR + (p * 16 + v_kof) * 2;
                uint32_t vh4[4];
                ldsm_x4_trans(vh4, kvb + KVVF + bo);
                uint32_t bh0[2] = {vh4[0], vh4[1]}, bh1[2] = {vh4[2], vh4[3]};
                mma_f16(o[2 * p],     ph, bh0);
                mma_f16(o[2 * p + 1], ph, bh1);
            }
        }

        if (t < 15) CP_WAIT(0);  // next tile arrived
        __syncthreads();          // all data visible, compute t done
    }

    // ---- Epilogue: normalize, write bf16 hi/lo
    float inv0 = 1.0f / l0r, inv1 = 1.0f / l1r;
    int r0 = q0 + wid * 16 + gid;
    size_t ob = ((size_t)(b * SQ_ + r0)) * H_ + h * HD_;
#pragma unroll
    for (int nt = 0; nt < 8; nt++) {
        int c = nt * 8 + tig * 2;
        float x0 = o[nt][0] * inv0, x1 = o[nt][1] * inv0;
        float y0 = o[nt][2] * inv1, y1 = o[nt][3] * inv1;
        *(uint32_t*)(g_o_hi + ob + c) = pack_bf16(x0, x1);
        *(uint32_t*)(g_o_lo + ob + c) = pack_bf16(bf16_res(x0), bf16_res(x1));
        *(uint32_t*)(g_o_hi + ob + (size_t)8 * H_ + c) = pack_bf16(y0, y1);
        *(uint32_t*)(g_o_lo + ob + (size_t)8 * H_ + c) =
            pack_bf16(bf16_res(y0), bf16_res(y1));
    }
}

// ---------------------------------------------------------------------------
extern "C" void kernel_launch(void* const* d_in, const int* in_sizes, int n_in,
                              void* d_out, int out_size) {
    const float* Xq  = (const float*)d_in[0];
    const float* Xkv = (const float*)d_in[1];
    const void*  mask = d_in[2];
    const float* Wq = (const float*)d_in[3];
    const float* bq = (const float*)d_in[4];
    const float* Wk = (const float*)d_in[5];
    const float* bk = (const float*)d_in[6];
    const float* Wv = (const float*)d_in[7];
    const float* bv = (const float*)d_in[8];
    const float* Wo = (const float*)d_in[9];
    const float* bo = (const float*)d_in[10];
    float* out = (float*)d_out;

    __nv_bfloat16 *xqh, *xql, *xkh, *xkl;
    __nv_bfloat16 *qhi, *qlo, *khi, *klo, *ohi, *olo;
    __half* vf16;
    __nv_bfloat16 *wqh, *wql, *wkh, *wkl, *wvh, *wvl, *woh, *wol;
    cudaGetSymbolAddress((void**)&xqh, g_xq_hi);
    cudaGetSymbolAddress((void**)&xql, g_xq_lo);
    cudaGetSymbolAddress((void**)&xkh, g_xkv_hi);
    cudaGetSymbolAddress((void**)&xkl, g_xkv_lo);
    cudaGetSymbolAddress((void**)&qhi, g_q_hi);
    cudaGetSymbolAddress((void**)&qlo, g_q_lo);
    cudaGetSymbolAddress((void**)&khi, g_k_hi);
    cudaGetSymbolAddress((void**)&klo, g_k_lo);
    cudaGetSymbolAddress((void**)&vf16, g_v_f16);
    cudaGetSymbolAddress((void**)&ohi, g_o_hi);
    cudaGetSymbolAddress((void**)&olo, g_o_lo);
    cudaGetSymbolAddress((void**)&wqh, g_wq_hi);
    cudaGetSymbolAddress((void**)&wql, g_wq_lo);
    cudaGetSymbolAddress((void**)&wkh, g_wk_hi);
    cudaGetSymbolAddress((void**)&wkl, g_wk_lo);
    cudaGetSymbolAddress((void**)&wvh, g_wv_hi);
    cudaGetSymbolAddress((void**)&wvl, g_wv_lo);
    cudaGetSymbolAddress((void**)&woh, g_wo_hi);
    cudaGetSymbolAddress((void**)&wol, g_wo_lo);

    cudaFuncSetAttribute(flash_attn_tc_kernel,
                         cudaFuncAttributeMaxDynamicSharedMemorySize,
                         ATTN4_SMEM);
    cudaFuncSetAttribute(tc_gemm_kernel,
                         cudaFuncAttributeMaxDynamicSharedMemorySize,
                         TCG_SMEM);

    // Mask prep
    mask_detect_kernel<<<1, 256>>>((const int*)mask);
    mask_expand_kernel<<<(B_ * SKV_ + 255) / 256, 256>>>(mask);

    // Convert input activations (hi/lo split)
    const int n4 = MROWS * DQ_ / 4;
    convert_hilo_kernel<<<(n4 + 255) / 256, 256>>>(Xq, xqh, xql, n4);
    convert_hilo_kernel<<<(n4 + 255) / 256, 256>>>(Xkv, xkh, xkl, n4);

    // Transpose + convert weights to [N][K] bf16 hi/lo
    dim3 tgrid(DQ_ / 32, H_ / 32), tblk(256);
    transpose_convert_kernel<<<tgrid, tblk>>>(Wq, wqh, wql, DQ_, H_);
    transpose_convert_kernel<<<tgrid, tblk>>>(Wk, wkh, wkl, DQ_, H_);
    transpose_convert_kernel<<<tgrid, tblk>>>(Wv, wvh, wvl, DQ_, H_);
    transpose_convert_kernel<<<tgrid, tblk>>>(Wo, woh, wol, H_, DQ_);

    // Projections (Q folds 1/sqrt(HD) = 0.125): Q/K split bf16, V fp16
    dim3 ggrid(H_ / 128, MROWS / 128);  // (8, 32)
    tc_gemm_kernel<<<ggrid, 256, TCG_SMEM>>>(xqh, xql, wqh, wql, bq,
                                             nullptr, qhi, qlo, nullptr, 1, 0.125f);
    tc_gemm_kernel<<<ggrid, 256, TCG_SMEM>>>(xkh, xkl, wkh, wkl, bk,
                                             nullptr, khi, klo, nullptr, 1, 1.0f);
    tc_gemm_kernel<<<ggrid, 256, TCG_SMEM>>>(xkh, xkl, wvh, wvl, bv,
                                             nullptr, nullptr, nullptr, vf16, 2, 1.0f);

    // Attention (HMMA: split-bf16 QK^T, fp16 PV)
    dim3 agrid(SQ_ / 128, B_ * NH_);  // (16, 32)
    flash_attn_tc_kernel<<<agrid, 256, ATTN4_SMEM>>>();

    // Output projection (fp32 out)
    tc_gemm_kernel<<<ggrid, 256, TCG_SMEM>>>(ohi, olo, woh, wol, bo,
                                             out, nullptr, nullptr, nullptr, 0, 1.0f);
}

// round 15
// speedup vs baseline: 3.3417x; 1.0852x over previous
#include <cuda_runtime.h>
#include <cuda_bf16.h>
#include <cuda_fp16.h>
#include <cstdint>

// Problem constants
#define B_    2
#define SQ_   2048
#define SKV_  2048
#define H_    1024
#define NH_   16
#define HD_   64
#define DQ_   1024
#define MROWS (B_ * SQ_)   // 4096

// ---------------------------------------------------------------------------
// Scratch (device globals; no allocation allowed)
// ---------------------------------------------------------------------------
__device__ float g_maskf[B_ * SKV_];   // additive mask: 0 or -1e30
__device__ int   g_mask_is_bytes;

// bf16 hi/lo split operands (GEMM inputs)
__device__ __nv_bfloat16 g_xq_hi[MROWS * DQ_],  g_xq_lo[MROWS * DQ_];
__device__ __nv_bfloat16 g_xkv_hi[MROWS * DQ_], g_xkv_lo[MROWS * DQ_];
// projection outputs: Q fp16 hi/lo (2-term QK^T); K, V plain fp16
__device__ __half g_q_h16[MROWS * H_], g_q_l16[MROWS * H_];
__device__ __half g_k_f16[MROWS * H_];
__device__ __half g_v_f16[MROWS * H_];
// attention output, bf16 hi/lo
__device__ __nv_bfloat16 g_o_hi[MROWS * H_], g_o_lo[MROWS * H_];
// weights transposed to [N][K] K-major
__device__ __nv_bfloat16 g_wq_hi[H_ * DQ_], g_wq_lo[H_ * DQ_];
__device__ __nv_bfloat16 g_wk_hi[H_ * DQ_], g_wk_lo[H_ * DQ_];
__device__ __nv_bfloat16 g_wv_hi[H_ * DQ_], g_wv_lo[H_ * DQ_];
__device__ __nv_bfloat16 g_wo_hi[DQ_ * H_], g_wo_lo[DQ_ * H_];

// ---------------------------------------------------------------------------
// PTX helpers (sm_80-era only: valid under generic sm_103 PTX target)
// ---------------------------------------------------------------------------
__device__ __forceinline__ uint32_t smem_u32(const void* p) {
    uint32_t a;
    asm("{ .reg .u64 t; cvta.to.shared.u64 t, %1; cvt.u32.u64 %0, t; }"
        : "=r"(a) : "l"(p));
    return a;
}
__device__ __forceinline__ void cp_async16(uint32_t sdst, const void* gsrc) {
    asm volatile("cp.async.cg.shared.global [%0], [%1], 16;"
                 :: "r"(sdst), "l"(gsrc) : "memory");
}
#define CP_COMMIT() asm volatile("cp.async.commit_group;" ::: "memory")
#define CP_WAIT(n)  asm volatile("cp.async.wait_group %0;" :: "n"(n) : "memory")

__device__ __forceinline__ void ldsm_x4(uint32_t* r, uint32_t addr) {
    asm volatile("ldmatrix.sync.aligned.m8n8.x4.shared.b16 {%0,%1,%2,%3}, [%4];"
                 : "=r"(r[0]), "=r"(r[1]), "=r"(r[2]), "=r"(r[3]) : "r"(addr));
}
__device__ __forceinline__ void ldsm_x4_trans(uint32_t* r, uint32_t addr) {
    asm volatile("ldmatrix.sync.aligned.m8n8.x4.trans.shared.b16 {%0,%1,%2,%3}, [%4];"
                 : "=r"(r[0]), "=r"(r[1]), "=r"(r[2]), "=r"(r[3]) : "r"(addr));
}
__device__ __forceinline__ void mma_bf16(float* c, const uint32_t* a,
                                         const uint32_t* b) {
    asm volatile(
        "mma.sync.aligned.m16n8k16.row.col.f32.bf16.bf16.f32 "
        "{%0,%1,%2,%3}, {%4,%5,%6,%7}, {%8,%9}, {%0,%1,%2,%3};"
        : "+f"(c[0]), "+f"(c[1]), "+f"(c[2]), "+f"(c[3])
        : "r"(a[0]), "r"(a[1]), "r"(a[2]), "r"(a[3]), "r"(b[0]), "r"(b[1]));
}
__device__ __forceinline__ void mma_f16(float* c, const uint32_t* a,
                                        const uint32_t* b) {
    asm volatile(
        "mma.sync.aligned.m16n8k16.row.col.f32.f16.f16.f32 "
        "{%0,%1,%2,%3}, {%4,%5,%6,%7}, {%8,%9}, {%0,%1,%2,%3};"
        : "+f"(c[0]), "+f"(c[1]), "+f"(c[2]), "+f"(c[3])
        : "r"(a[0]), "r"(a[1]), "r"(a[2]), "r"(a[3]), "r"(b[0]), "r"(b[1]));
}
// pack two fp32 -> bf16x2 (first arg -> low half)
__device__ __forceinline__ uint32_t pack_bf16(float lo, float hi) {
    uint32_t r;
    asm("cvt.rn.bf16x2.f32 %0, %1, %2;" : "=r"(r) : "f"(hi), "f"(lo));
    return r;
}
// pack two fp32 -> f16x2 (first arg -> low half)
__device__ __forceinline__ uint32_t pack_f16(float lo, float hi) {
    __half2 h2 = __floats2half2_rn(lo, hi);
    return *(uint32_t*)&h2;
}
__device__ __forceinline__ float bf16_res(float x) {
    return x - __bfloat162float(__float2bfloat16(x));
}
__device__ __forceinline__ float f16_res(float x) {
    return x - __half2float(__float2half_rn(x));
}

// ---------------------------------------------------------------------------
// Mask dtype detection + expansion (verified round 3)
// ---------------------------------------------------------------------------
__global__ void mask_detect_kernel(const int* __restrict__ m) {
    __shared__ int bad;
    if (threadIdx.x == 0) bad = 0;
    __syncthreads();
    for (int i = threadIdx.x; i < 1024; i += blockDim.x) {
        unsigned v = (unsigned)m[i];
        if (v > 1u) atomicOr(&bad, 1);
    }
    __syncthreads();
    if (threadIdx.x == 0) g_mask_is_bytes = bad;
}
__global__ void mask_expand_kernel(const void* __restrict__ m) {
    int i = blockIdx.x * blockDim.x + threadIdx.x;
    if (i >= B_ * SKV_) return;
    int v;
    if (g_mask_is_bytes) v = ((const unsigned char*)m)[i];
    else                 v = ((const int*)m)[i];
    g_maskf[i] = v ? -1e30f : 0.0f;
}

// ---------------------------------------------------------------------------
// fp32 -> bf16 hi/lo split (elementwise, for kernel inputs)
// ---------------------------------------------------------------------------
__global__ void convert_hilo_kernel(const float* __restrict__ in,
                                    __nv_bfloat16* __restrict__ hi,
                                    __nv_bfloat16* __restrict__ lo, int n4) {
    int i = blockIdx.x * blockDim.x + threadIdx.x;
    if (i >= n4) return;
    float4 v = ((const float4*)in)[i];
    __nv_bfloat16 h[4], l[4];
    float f[4] = {v.x, v.y, v.z, v.w};
#pragma unroll
    for (int j = 0; j < 4; j++) {
        h[j] = __float2bfloat16(f[j]);
        l[j] = __float2bfloat16(f[j] - __bfloat162float(h[j]));
    }
    ((uint2*)hi)[i] = *(uint2*)h;
    ((uint2*)lo)[i] = *(uint2*)l;
}

// ---------------------------------------------------------------------------
// W [K x N] fp32 -> Wt [N x K] bf16 hi/lo (transpose through smem)
// ---------------------------------------------------------------------------
__global__ void transpose_convert_kernel(const float* __restrict__ W,
                                         __nv_bfloat16* __restrict__ Thi,
                                         __nv_bfloat16* __restrict__ Tlo,
                                         int Kd, int Nd) {
    __shared__ float tile[32][33];
    int n0 = blockIdx.x * 32, k0 = blockIdx.y * 32;
    int tx = threadIdx.x & 31, ty = threadIdx.x >> 5;
    for (int r = ty; r < 32; r += 8)
        tile[r][tx] = W[(size_t)(k0 + r) * Nd + n0 + tx];
    __syncthreads();
    for (int r = ty; r < 32; r += 8) {
        float v = tile[tx][r];
        __nv_bfloat16 h = __float2bfloat16(v);
        __nv_bfloat16 l = __float2bfloat16(v - __bfloat162float(h));
        Thi[(size_t)(n0 + r) * Kd + k0 + tx] = h;
        Tlo[(size_t)(n0 + r) * Kd + k0 + tx] = l;
    }
}

// ---------------------------------------------------------------------------
// Split-bf16 tensor-core GEMM (validated R10/R12/R14).
// Epilogue mode: 0 = fp32 C, 1 = bf16 hi/lo (Chi/Clo),
//                2 = fp16 single (Cf16), 3 = fp16 hi/lo (Cf16/Cf16l).
// ---------------------------------------------------------------------------
#define GSTRIDE 80
#define ARR_BYTES (128 * GSTRIDE)
#define STAGE_BYTES (4 * ARR_BYTES)
#define TCG_SMEM (2 * STAGE_BYTES)

__global__ __launch_bounds__(256)
void tc_gemm_kernel(const __nv_bfloat16* __restrict__ Ahi,
                    const __nv_bfloat16* __restrict__ Alo,
                    const __nv_bfloat16* __restrict__ Bhi,
                    const __nv_bfloat16* __restrict__ Blo,
                    const float* __restrict__ bias, float* __restrict__ C,
                    __nv_bfloat16* __restrict__ Chi,
                    __nv_bfloat16* __restrict__ Clo,
                    __half* __restrict__ Cf16,
                    __half* __restrict__ Cf16l,
                    int mode, float scale) {
    extern __shared__ char smem[];
    const uint32_t sb = smem_u32(smem);
    const int tid = threadIdx.x;
    const int wid = tid >> 5;
    const int lane = tid & 31;
    const int wm = wid >> 2;
    const int wn = wid & 3;
    const int bm = blockIdx.y * 128;
    const int bn = blockIdx.x * 128;

    const int ld_row = tid >> 2;
    const int ld_seg = tid & 3;

    float acc[4][4][4];
#pragma unroll
    for (int i = 0; i < 4; i++)
#pragma unroll
        for (int j = 0; j < 4; j++)
#pragma unroll
            for (int q = 0; q < 4; q++) acc[i][j][q] = 0.0f;

    auto issue = [&](int ch, int s) {
        const uint32_t so = sb + s * STAGE_BYTES;
        const int kbase = ch * 32;
#pragma unroll
        for (int it = 0; it < 2; it++) {
            int row = ld_row + it * 64;
            uint32_t soff = row * GSTRIDE + ld_seg * 16;
            size_t ga = (size_t)(bm + row) * 1024 + kbase + ld_seg * 8;
            size_t gb = (size_t)(bn + row) * 1024 + kbase + ld_seg * 8;
            cp_async16(so + soff,                 Ahi + ga);
            cp_async16(so + ARR_BYTES + soff,     Alo + ga);
            cp_async16(so + 2 * ARR_BYTES + soff, Bhi + gb);
            cp_async16(so + 3 * ARR_BYTES + soff, Blo + gb);
        }
    };

    issue(0, 0);
    CP_COMMIT();

    const uint32_t a_row = (uint32_t)(wm * 64 + (lane & 15));
    const uint32_t a_kof = (uint32_t)((lane & 16) >> 1);
    const uint32_t b_row = (uint32_t)(wn * 32 + ((lane & 16) >> 1) + (lane & 7));
    const uint32_t b_kof = (uint32_t)(lane & 8);

    for (int ch = 0; ch < 32; ch++) {
        const int s = ch & 1;
        if (ch < 31) { issue(ch + 1, s ^ 1); CP_COMMIT(); CP_WAIT(1); }
        else         { CP_WAIT(0); }
        __syncthreads();

        const uint32_t so = sb + s * STAGE_BYTES;
#pragma unroll
        for (int ks = 0; ks < 32; ks += 16) {
            uint32_t ah[4][4], al[4][4], bh[4][2], bl[4][2];
#pragma unroll
            for (int mt = 0; mt < 4; mt++) {
                uint32_t ao = (a_row + mt * 16) * GSTRIDE + (ks + a_kof) * 2;
                ldsm_x4(ah[mt], so + ao);
                ldsm_x4(al[mt], so + ARR_BYTES + ao);
            }
#pragma unroll
            for (int p = 0; p < 2; p++) {
                uint32_t bo = (b_row + p * 16) * GSTRIDE + (ks + b_kof) * 2;
                uint32_t rh[4], rl[4];
                ldsm_x4(rh, so + 2 * ARR_BYTES + bo);
                ldsm_x4(rl, so + 3 * ARR_BYTES + bo);
                bh[2 * p][0] = rh[0]; bh[2 * p][1] = rh[1];
                bh[2 * p + 1][0] = rh[2]; bh[2 * p + 1][1] = rh[3];
                bl[2 * p][0] = rl[0]; bl[2 * p][1] = rl[1];
                bl[2 * p + 1][0] = rl[2]; bl[2 * p + 1][1] = rl[3];
            }
#pragma unroll
            for (int mt = 0; mt < 4; mt++)
#pragma unroll
                for (int nt = 0; nt < 4; nt++) {
                    mma_bf16(acc[mt][nt], ah[mt], bh[nt]);
                    mma_bf16(acc[mt][nt], ah[mt], bl[nt]);
                    mma_bf16(acc[mt][nt], al[mt], bh[nt]);
                }
        }
        __syncthreads();
    }

    const int gid = lane >> 2;
    const int tig = lane & 3;
#pragma unroll
    for (int mt = 0; mt < 4; mt++) {
        int r0 = bm + wm * 64 + mt * 16 + gid;
#pragma unroll
        for (int nt = 0; nt < 4; nt++) {
            int c0 = bn + wn * 32 + nt * 8 + tig * 2;
            float b0 = __ldg(&bias[c0]), b1 = __ldg(&bias[c0 + 1]);
            float v00 = scale * (acc[mt][nt][0] + b0);
            float v01 = scale * (acc[mt][nt][1] + b1);
            float v10 = scale * (acc[mt][nt][2] + b0);
            float v11 = scale * (acc[mt][nt][3] + b1);
            size_t o0 = (size_t)r0 * 1024 + c0;
            size_t o1 = (size_t)(r0 + 8) * 1024 + c0;
            if (mode == 0) {
                *(float2*)(C + o0) = make_float2(v00, v01);
                *(float2*)(C + o1) = make_float2(v10, v11);
            } else if (mode == 1) {
                *(uint32_t*)(Chi + o0) = pack_bf16(v00, v01);
                *(uint32_t*)(Clo + o0) = pack_bf16(bf16_res(v00), bf16_res(v01));
                *(uint32_t*)(Chi + o1) = pack_bf16(v10, v11);
                *(uint32_t*)(Clo + o1) = pack_bf16(bf16_res(v10), bf16_res(v11));
            } else if (mode == 2) {
                *(uint32_t*)(Cf16 + o0) = pack_f16(v00, v01);
                *(uint32_t*)(Cf16 + o1) = pack_f16(v10, v11);
            } else {
                *(uint32_t*)(Cf16 + o0)  = pack_f16(v00, v01);
                *(uint32_t*)(Cf16l + o0) = pack_f16(f16_res(v00), f16_res(v01));
                *(uint32_t*)(Cf16 + o1)  = pack_f16(v10, v11);
                *(uint32_t*)(Cf16l + o1) = pack_f16(f16_res(v10), f16_res(v11));
            }
        }
    }
}

// ---------------------------------------------------------------------------
// HMMA flash attention v4: QK^T = (qh+ql)·k, all fp16 (2-term; error = K's
// fp16 rounding ~2e-4 abs on scores). PV fp16 single-term (validated R14).
// smem: Q hi/lo 36864 + 2 stages x (Kf16+Vf16 = 36864) + mask = 111104 B.
// ---------------------------------------------------------------------------
#define RSTR 144
#define AQH2 0
#define AQL2 18432
#define KVST(s) (36864 + (s) * 36864)
#define KVKF 0
#define KVVF 18432
#define AMS2 110592
#define ATTN5_SMEM 111104

__global__ __launch_bounds__(256, 1)
void flash_attn_tc_kernel() {
    extern __shared__ char smem[];
    const uint32_t sb = smem_u32(smem);
    float* Ms = (float*)(smem + AMS2);

    const int tid = threadIdx.x;
    const int wid = tid >> 5;
    const int lane = tid & 31;
    const int gid = lane >> 2;
    const int tig = lane & 3;
    const int b = blockIdx.y >> 4;
    const int h = blockIdx.y & 15;
    const int q0 = blockIdx.x * 128;

    const size_t qbase  = ((size_t)(b * SQ_ + q0)) * H_ + h * HD_;
    const size_t kvbase = ((size_t)(b * SKV_)) * H_ + h * HD_;
    const float* mg = g_maskf + b * SKV_;

    auto issue_kv = [&](int t, int s) {
        const uint32_t base = sb + KVST(s);
        const int kv0 = t * 128;
#pragma unroll
        for (int it = 0; it < 4; it++) {
            int idx = tid + it * 256;       // 0..1023
            int row = idx >> 3, ch = idx & 7;
            uint32_t soff = row * RSTR + ch * 16;
            size_t go = kvbase + (size_t)(kv0 + row) * H_ + ch * 8;
            cp_async16(base + KVKF + soff, g_k_f16 + go);
            cp_async16(base + KVVF + soff, g_v_f16 + go);
        }
    };

    // Q load (once)
#pragma unroll
    for (int it = 0; it < 4; it++) {
        int idx = tid + it * 256;
        int row = idx >> 3, ch = idx & 7;
        uint32_t soff = row * RSTR + ch * 16;
        size_t go = qbase + (size_t)row * H_ + ch * 8;
        cp_async16(sb + AQH2 + soff, g_q_h16 + go);
        cp_async16(sb + AQL2 + soff, g_q_l16 + go);
    }
    CP_COMMIT();
    issue_kv(0, 0);
    CP_COMMIT();
    CP_WAIT(0);
    __syncthreads();

    // Hoist Q fragments (fp16 hi/lo)
    const uint32_t a_row = (uint32_t)(wid * 16 + (lane & 15));
    const uint32_t a_kof = (uint32_t)((lane & 16) >> 1);
    const uint32_t b_sel = (uint32_t)(((lane & 16) >> 1) + (lane & 7));
    const uint32_t b_kof = (uint32_t)(lane & 8);
    const uint32_t v_sel = (uint32_t)(lane & 15);
    const uint32_t v_kof = (uint32_t)((lane >> 4) * 8);
    uint32_t qh[4][4], ql[4][4];
#pragma unroll
    for (int ks = 0; ks < 4; ks++) {
        uint32_t ao = a_row * RSTR + (ks * 16 + a_kof) * 2;
        ldsm_x4(qh[ks], sb + AQH2 + ao);
        ldsm_x4(ql[ks], sb + AQL2 + ao);
    }

    float o[8][4];
#pragma unroll
    for (int nt = 0; nt < 8; nt++)
#pragma unroll
        for (int j = 0; j < 4; j++) o[nt][j] = 0.0f;
    float m0r = -1e30f, m1r = -1e30f, l0r = 0.0f, l1r = 0.0f;

    for (int t = 0; t < 16; t++) {
        const int s = t & 1;
        const uint32_t kvb = sb + KVST(s);

        if (tid < 128) Ms[tid] = mg[t * 128 + tid];
        if (t < 15) { issue_kv(t + 1, s ^ 1); CP_COMMIT(); }
        __syncthreads();  // Ms visible; stage s^1 free of readers

        // ---- S = Q K^T : 16 n-tiles, 4 k-steps, 2-term fp16
        float sc[16][4];
#pragma unroll
        for (int nt = 0; nt < 16; nt++)
#pragma unroll
            for (int j = 0; j < 4; j++) sc[nt][j] = 0.0f;
#pragma unroll
        for (int ks = 0; ks < 4; ks++) {
#pragma unroll
            for (int p = 0; p < 8; p++) {
                uint32_t bo = (p * 16 + b_sel) * RSTR + (ks * 16 + b_kof) * 2;
                uint32_t kh4[4];
                ldsm_x4(kh4, kvb + KVKF + bo);
                uint32_t bh0[2] = {kh4[0], kh4[1]}, bh1[2] = {kh4[2], kh4[3]};
                mma_f16(sc[2 * p],     qh[ks], bh0);
                mma_f16(sc[2 * p],     ql[ks], bh0);
                mma_f16(sc[2 * p + 1], qh[ks], bh1);
                mma_f16(sc[2 * p + 1], ql[ks], bh1);
            }
        }

        // ---- Mask + online softmax
        float mt0 = -1e30f, mt1 = -1e30f;
#pragma unroll
        for (int nt = 0; nt < 16; nt++) {
            float mk0 = Ms[nt * 8 + tig * 2];
            float mk1 = Ms[nt * 8 + tig * 2 + 1];
            sc[nt][0] += mk0; sc[nt][1] += mk1;
            sc[nt][2] += mk0; sc[nt][3] += mk1;
            mt0 = fmaxf(mt0, fmaxf(sc[nt][0], sc[nt][1]));
            mt1 = fmaxf(mt1, fmaxf(sc[nt][2], sc[nt][3]));
        }
        mt0 = fmaxf(mt0, __shfl_xor_sync(0xffffffffu, mt0, 1));
        mt0 = fmaxf(mt0, __shfl_xor_sync(0xffffffffu, mt0, 2));
        mt1 = fmaxf(mt1, __shfl_xor_sync(0xffffffffu, mt1, 1));
        mt1 = fmaxf(mt1, __shfl_xor_sync(0xffffffffu, mt1, 2));
        float mn0 = fmaxf(m0r, mt0), mn1 = fmaxf(m1r, mt1);
        float so0 = __expf(m0r - mn0), so1 = __expf(m1r - mn1);
        float sum0 = 0.0f, sum1 = 0.0f;
#pragma unroll
        for (int nt = 0; nt < 16; nt++) {
            sc[nt][0] = __expf(sc[nt][0] - mn0);
            sc[nt][1] = __expf(sc[nt][1] - mn0);
            sc[nt][2] = __expf(sc[nt][2] - mn1);
            sc[nt][3] = __expf(sc[nt][3] - mn1);
            sum0 += sc[nt][0] + sc[nt][1];
            sum1 += sc[nt][2] + sc[nt][3];
        }
        sum0 += __shfl_xor_sync(0xffffffffu, sum0, 1);
        sum0 += __shfl_xor_sync(0xffffffffu, sum0, 2);
        sum1 += __shfl_xor_sync(0xffffffffu, sum1, 1);
        sum1 += __shfl_xor_sync(0xffffffffu, sum1, 2);
        l0r = l0r * so0 + sum0;  m0r = mn0;
        l1r = l1r * so1 + sum1;  m1r = mn1;
#pragma unroll
        for (int nt = 0; nt < 8; nt++) {
            o[nt][0] *= so0; o[nt][1] *= so0;
            o[nt][2] *= so1; o[nt][3] *= so1;
        }

        // ---- O += P V : fp16 P, fp16 V, single term
#pragma unroll
        for (int kt = 0; kt < 8; kt++) {
            uint32_t ph[4];
            ph[0] = pack_f16(sc[2 * kt][0],     sc[2 * kt][1]);
            ph[1] = pack_f16(sc[2 * kt][2],     sc[2 * kt][3]);
            ph[2] = pack_f16(sc[2 * kt + 1][0], sc[2 * kt + 1][1]);
            ph[3] = pack_f16(sc[2 * kt + 1][2], sc[2 * kt + 1][3]);
#pragma unroll
            for (int p = 0; p < 4; p++) {
                uint32_t bo = (kt * 16 + v_sel) * RSTR + (p * 16 + v_kof) * 2;
                uint32_t vh4[4];
                ldsm_x4_trans(vh4, kvb + KVVF + bo);
                uint32_t bh0[2] = {vh4[0], vh4[1]}, bh1[2] = {vh4[2], vh4[3]};
                mma_f16(o[2 * p],     ph, bh0);
                mma_f16(o[2 * p + 1], ph, bh1);
            }
        }

        if (t < 15) CP_WAIT(0);  // next tile arrived
        __syncthreads();          // all data visible, compute t done
    }

    // ---- Epilogue: normalize, write bf16 hi/lo
    float inv0 = 1.0f / l0r, inv1 = 1.0f / l1r;
    int r0 = q0 + wid * 16 + gid;
    size_t ob = ((size_t)(b * SQ_ + r0)) * H_ + h * HD_;
#pragma unroll
    for (int nt = 0; nt < 8; nt++) {
        int c = nt * 8 + tig * 2;
        float x0 = o[nt][0] * inv0, x1 = o[nt][1] * inv0;
        float y0 = o[nt][2] * inv1, y1 = o[nt][3] * inv1;
        *(uint32_t*)(g_o_hi + ob + c) = pack_bf16(x0, x1);
        *(uint32_t*)(g_o_lo + ob + c) = pack_bf16(bf16_res(x0), bf16_res(x1));
        *(uint32_t*)(g_o_hi + ob + (size_t)8 * H_ + c) = pack_bf16(y0, y1);
        *(uint32_t*)(g_o_lo + ob + (size_t)8 * H_ + c) =
            pack_bf16(bf16_res(y0), bf16_res(y1));
    }
}

// ---------------------------------------------------------------------------
extern "C" void kernel_launch(void* const* d_in, const int* in_sizes, int n_in,
                              void* d_out, int out_size) {
    const float* Xq  = (const float*)d_in[0];
    const float* Xkv = (const float*)d_in[1];
    const void*  mask = d_in[2];
    const float* Wq = (const float*)d_in[3];
    const float* bq = (const float*)d_in[4];
    const float* Wk = (const float*)d_in[5];
    const float* bk = (const float*)d_in[6];
    const float* Wv = (const float*)d_in[7];
    const float* bv = (const float*)d_in[8];
    const float* Wo = (const float*)d_in[9];
    const float* bo = (const float*)d_in[10];
    float* out = (float*)d_out;

    __nv_bfloat16 *xqh, *xql, *xkh, *xkl, *ohi, *olo;
    __half *qh16, *ql16, *kf16, *vf16;
    __nv_bfloat16 *wqh, *wql, *wkh, *wkl, *wvh, *wvl, *woh, *wol;
    cudaGetSymbolAddress((void**)&xqh, g_xq_hi);
    cudaGetSymbolAddress((void**)&xql, g_xq_lo);
    cudaGetSymbolAddress((void**)&xkh, g_xkv_hi);
    cudaGetSymbolAddress((void**)&xkl, g_xkv_lo);
    cudaGetSymbolAddress((void**)&qh16, g_q_h16);
    cudaGetSymbolAddress((void**)&ql16, g_q_l16);
    cudaGetSymbolAddress((void**)&kf16, g_k_f16);
    cudaGetSymbolAddress((void**)&vf16, g_v_f16);
    cudaGetSymbolAddress((void**)&ohi, g_o_hi);
    cudaGetSymbolAddress((void**)&olo, g_o_lo);
    cudaGetSymbolAddress((void**)&wqh, g_wq_hi);
    cudaGetSymbolAddress((void**)&wql, g_wq_lo);
    cudaGetSymbolAddress((void**)&wkh, g_wk_hi);
    cudaGetSymbolAddress((void**)&wkl, g_wk_lo);
    cudaGetSymbolAddress((void**)&wvh, g_wv_hi);
    cudaGetSymbolAddress((void**)&wvl, g_wv_lo);
    cudaGetSymbolAddress((void**)&woh, g_wo_hi);
    cudaGetSymbolAddress((void**)&wol, g_wo_lo);

    cudaFuncSetAttribute(flash_attn_tc_kernel,
                         cudaFuncAttributeMaxDynamicSharedMemorySize,
                         ATTN5_SMEM);
    cudaFuncSetAttribute(tc_gemm_kernel,
                         cudaFuncAttributeMaxDynamicSharedMemorySize,
                         TCG_SMEM);

    // Mask prep
    mask_detect_kernel<<<1, 256>>>((const int*)mask);
    mask_expand_kernel<<<(B_ * SKV_ + 255) / 256, 256>>>(mask);

    // Convert input activations (hi/lo split)
    const int n4 = MROWS * DQ_ / 4;
    convert_hilo_kernel<<<(n4 + 255) / 256, 256>>>(Xq, xqh, xql, n4);
    convert_hilo_kernel<<<(n4 + 255) / 256, 256>>>(Xkv, xkh, xkl, n4);

    // Transpose + convert weights to [N][K] bf16 hi/lo
    dim3 tgrid(DQ_ / 32, H_ / 32), tblk(256);
    transpose_convert_kernel<<<tgrid, tblk>>>(Wq, wqh, wql, DQ_, H_);
    transpose_convert_kernel<<<tgrid, tblk>>>(Wk, wkh, wkl, DQ_, H_);
    transpose_convert_kernel<<<tgrid, tblk>>>(Wv, wvh, wvl, DQ_, H_);
    transpose_convert_kernel<<<tgrid, tblk>>>(Wo, woh, wol, H_, DQ_);

    // Projections (Q folds 1/sqrt(HD) = 0.125):
    //   Q -> fp16 hi/lo (mode 3); K, V -> fp16 single (mode 2)
    dim3 ggrid(H_ / 128, MROWS / 128);  // (8, 32)
    tc_gemm_kernel<<<ggrid, 256, TCG_SMEM>>>(xqh, xql, wqh, wql, bq,
        nullptr, nullptr, nullptr, qh16, ql16, 3, 0.125f);
    tc_gemm_kernel<<<ggrid, 256, TCG_SMEM>>>(xkh, xkl, wkh, wkl, bk,
        nullptr, nullptr, nullptr, kf16, nullptr, 2, 1.0f);
    tc_gemm_kernel<<<ggrid, 256, TCG_SMEM>>>(xkh, xkl, wvh, wvl, bv,
        nullptr, nullptr, nullptr, vf16, nullptr, 2, 1.0f);

    // Attention (HMMA: 2-term fp16 QK^T, fp16 PV)
    dim3 agrid(SQ_ / 128, B_ * NH_);  // (16, 32)
    flash_attn_tc_kernel<<<agrid, 256, ATTN5_SMEM>>>();

    // Output projection (fp32 out)
    tc_gemm_kernel<<<ggrid, 256, TCG_SMEM>>>(ohi, olo, woh, wol, bo,
        out, nullptr, nullptr, nullptr, nullptr, 0, 1.0f);
}